// round 1
// baseline (speedup 1.0000x reference)
#include <cuda_runtime.h>
#include <math.h>

// Problem dims (fixed)
#define Bb   2048
#define Nn   128
#define Dd   512
#define HIDD 2048
#define Hh   8
#define DHh  64

// ---------------- scratch (device globals; no allocations) ----------------
__device__ float g_H1[Bb * HIDD];
__device__ float g_H2[Bb * HIDD];
__device__ float g_emb[Bb * Dd];
__device__ float g_q[Bb * Dd];
__device__ float g_r[Bb * Hh * Dd];
__device__ float g_c[Bb * Hh * Dd];
__device__ float g_ctx[Bb * Dd];
__device__ float g_WkT[Dd * Dd];
__device__ float g_bnS[HIDD];
__device__ float g_bnT[HIDD];

// ---------------- generic fp32 SGEMM ----------------
// C[m,n] = scale * sum_k A'[m,k] * B[k,n] + bias[n]; optional tanh epilogue.
// A' = A (or BN-transformed: A*bnS[k]+bnT[k]). A: row-major lda. B: row stride ldb.
#define BM 128
#define BN 128
#define BKK 16
#define TM 8
#define TN 8

template <bool DOTANH, bool DOBN>
__global__ __launch_bounds__(256) void sgemm(
    const float* __restrict__ A, int lda,
    const float* __restrict__ B, int ldb,
    float* __restrict__ C, int ldc,
    const float* __restrict__ bias,
    const float* __restrict__ bnS, const float* __restrict__ bnT,
    int M, int N, int K, float scale)
{
    __shared__ float As[BKK][BM + 4];
    __shared__ float Bs[BKK][BN + 4];

    const int tid = threadIdx.x;
    const int row0 = blockIdx.y * BM;
    const int col0 = blockIdx.x * BN;
    const int tmBase = (tid / 16) * TM;
    const int tnBase = (tid % 16) * TN;

    const int ak = tid % 16;     // A loader: k within tile
    const int am = tid / 16;     // A loader: m base (stride 16)
    const int bn = tid % 128;    // B loader: n within tile
    const int bk0 = tid / 128;   // B loader: k base (stride 2)

    float acc[TM][TN];
#pragma unroll
    for (int i = 0; i < TM; i++)
#pragma unroll
        for (int j = 0; j < TN; j++) acc[i][j] = 0.f;

    for (int k0 = 0; k0 < K; k0 += BKK) {
        // load A tile (M always multiple of 128, K multiple of 16 in all uses)
        float s = 1.f, t = 0.f;
        if (DOBN) { s = bnS[k0 + ak]; t = bnT[k0 + ak]; }
#pragma unroll
        for (int it = 0; it < 8; ++it) {
            int m = am + it * 16;
            float v = A[(size_t)(row0 + m) * lda + (k0 + ak)];
            if (DOBN) v = v * s + t;
            As[ak][m] = v;
        }
        // load B tile (guard n for N=64 case)
#pragma unroll
        for (int it = 0; it < 8; ++it) {
            int kk = bk0 + it * 2;
            int n = col0 + bn;
            Bs[kk][bn] = (n < N) ? B[(size_t)(k0 + kk) * ldb + n] : 0.f;
        }
        __syncthreads();

#pragma unroll
        for (int kk = 0; kk < BKK; ++kk) {
            float a[TM], bb[TN];
#pragma unroll
            for (int i = 0; i < TM; i++) a[i] = As[kk][tmBase + i];
#pragma unroll
            for (int j = 0; j < TN; j++) bb[j] = Bs[kk][tnBase + j];
#pragma unroll
            for (int i = 0; i < TM; i++)
#pragma unroll
                for (int j = 0; j < TN; j++) acc[i][j] += a[i] * bb[j];
        }
        __syncthreads();
    }

#pragma unroll
    for (int i = 0; i < TM; i++) {
        int rrow = row0 + tmBase + i;
#pragma unroll
        for (int j = 0; j < TN; j++) {
            int col = col0 + tnBase + j;
            if (col < N) {
                float v = acc[i][j] * scale + (bias ? bias[col] : 0.f);
                if (DOTANH) v = tanhf(v);
                C[(size_t)rrow * ldc + col] = v;
            }
        }
    }
}

// ---------------- BatchNorm stats (per-column mean/var over 2048 rows) ----
__global__ void bn_stats_kernel(const float* __restrict__ H1,
                                const float* __restrict__ gamma,
                                const float* __restrict__ beta,
                                float* __restrict__ S, float* __restrict__ T)
{
    int col = blockIdx.x * blockDim.x + threadIdx.x;
    if (col >= HIDD) return;
    double s0 = 0, s1 = 0, s2 = 0, s3 = 0;
    double q0 = 0, q1 = 0, q2 = 0, q3 = 0;
    for (int rr = 0; rr < Bb; rr += 4) {
        float v0 = H1[(size_t)(rr + 0) * HIDD + col];
        float v1 = H1[(size_t)(rr + 1) * HIDD + col];
        float v2 = H1[(size_t)(rr + 2) * HIDD + col];
        float v3 = H1[(size_t)(rr + 3) * HIDD + col];
        s0 += v0; s1 += v1; s2 += v2; s3 += v3;
        q0 += (double)v0 * v0; q1 += (double)v1 * v1;
        q2 += (double)v2 * v2; q3 += (double)v3 * v3;
    }
    double sum = (s0 + s1) + (s2 + s3);
    double sq  = (q0 + q1) + (q2 + q3);
    double mu = sum / 2048.0;
    double var = sq / 2048.0 - mu * mu;
    float rstd = (float)rsqrt(var + 1e-5);
    float sc = gamma[col] * rstd;
    S[col] = sc;
    T[col] = beta[col] - (float)mu * sc;
}

// ---------------- 512x512 transpose (for Wk^T) ----------------
__global__ void transpose512(const float* __restrict__ in, float* __restrict__ out)
{
    __shared__ float t[32][33];
    int bx = blockIdx.x * 32, by = blockIdx.y * 32;
    int x = threadIdx.x, y = threadIdx.y;  // 32x8
#pragma unroll
    for (int i = 0; i < 32; i += 8)
        t[y + i][x] = in[(size_t)(by + y + i) * 512 + bx + x];
    __syncthreads();
#pragma unroll
    for (int i = 0; i < 32; i += 8)
        out[(size_t)(bx + y + i) * 512 + by + x] = t[x][y + i];
}

// ---------------- fused attention over neighbors ----------------
// For each batch b (one CTA):
//   scores[h,n] = sum_d nb[b,n,d] * r[b,h,d]   (r already includes 1/sqrt(DH))
//   mask n >= len -> -inf; softmax over n per head
//   c[b,h,d] = sum_n attn[h,n] * nb[b,n,d]
#define TILE_LD 132  // 128 + 4 pad (float4-aligned, conflict-free reads)
#define ATTN_SMEM ((4096 + 1024 + 128 * TILE_LD) * 4)

__global__ __launch_bounds__(256) void attn_kernel(
    const float* __restrict__ nb, const float* __restrict__ r,
    const int* __restrict__ lengths, float* __restrict__ c)
{
    extern __shared__ float sm[];
    float* r_s  = sm;          // [8][512]
    float* sc   = sm + 4096;   // [8][128] scores -> attn
    float* tile = sm + 5120;   // [128][TILE_LD]

    const int b = blockIdx.x;
    const int tid = threadIdx.x;
    const float NEG_INF = __int_as_float(0xff800000u);

    // load r[b] and zero scores
    {
        const float4* rg = (const float4*)(r + (size_t)b * 4096);
        float4* rs4 = (float4*)r_s;
        for (int i = tid; i < 1024; i += 256) rs4[i] = rg[i];
        for (int i = tid; i < 1024; i += 256) sc[i] = 0.f;
    }
    __syncthreads();

    const float* nbb = nb + (size_t)b * Nn * Dd;

    // ---- pass 1: scores ----
    for (int dt = 0; dt < 4; ++dt) {
#pragma unroll
        for (int it = 0; it < 16; ++it) {
            int l = tid + it * 256;
            int n = l >> 5, v = l & 31;
            float4 val = *(const float4*)(nbb + (size_t)n * Dd + dt * 128 + v * 4);
            *(float4*)&tile[n * TILE_LD + v * 4] = val;
        }
        __syncthreads();
#pragma unroll
        for (int o = 0; o < 4; ++o) {
            int idx = tid + o * 256;
            int h = idx >> 7, n = idx & 127;
            const float4* rp = (const float4*)(r_s + h * 512 + dt * 128);
            const float4* tp = (const float4*)(tile + n * TILE_LD);
            float a0 = 0, a1 = 0, a2 = 0, a3 = 0;
#pragma unroll
            for (int d4 = 0; d4 < 32; ++d4) {
                float4 tv = tp[d4], rv = rp[d4];
                a0 += tv.x * rv.x; a1 += tv.y * rv.y;
                a2 += tv.z * rv.z; a3 += tv.w * rv.w;
            }
            sc[idx] += (a0 + a1) + (a2 + a3);
        }
        __syncthreads();
    }

    // ---- softmax per head (warp w = head w) ----
    {
        int w = tid >> 5, lane = tid & 31;
        int len = lengths[b];
        float vals[4];
        float mx = NEG_INF;
#pragma unroll
        for (int kq = 0; kq < 4; kq++) {
            int n = lane + kq * 32;
            float v = (n < len) ? sc[w * 128 + n] : NEG_INF;
            vals[kq] = v;
            mx = fmaxf(mx, v);
        }
#pragma unroll
        for (int off = 16; off; off >>= 1)
            mx = fmaxf(mx, __shfl_xor_sync(0xffffffffu, mx, off));
        float sum = 0.f;
#pragma unroll
        for (int kq = 0; kq < 4; kq++) {
            float e = (vals[kq] == NEG_INF) ? 0.f : expf(vals[kq] - mx);
            vals[kq] = e;
            sum += e;
        }
#pragma unroll
        for (int off = 16; off; off >>= 1)
            sum += __shfl_xor_sync(0xffffffffu, sum, off);
        float inv = 1.f / sum;
#pragma unroll
        for (int kq = 0; kq < 4; kq++)
            sc[w * 128 + lane + kq * 32] = vals[kq] * inv;
    }
    __syncthreads();

    // ---- pass 2: c = attn^T @ nb ----
    float* cb = c + (size_t)b * 4096;
    const int h2 = tid >> 5;
    const int dbase = (tid & 31) * 4;
    for (int dt = 0; dt < 4; ++dt) {
#pragma unroll
        for (int it = 0; it < 16; ++it) {
            int l = tid + it * 256;
            int n = l >> 5, v = l & 31;
            float4 val = *(const float4*)(nbb + (size_t)n * Dd + dt * 128 + v * 4);
            *(float4*)&tile[n * TILE_LD + v * 4] = val;
        }
        __syncthreads();
        float x0 = 0, x1 = 0, x2 = 0, x3 = 0;
        const float* ap = sc + h2 * 128;
#pragma unroll 4
        for (int n = 0; n < 128; ++n) {
            float w = ap[n];
            float4 tv = *(const float4*)&tile[n * TILE_LD + dbase];
            x0 += w * tv.x; x1 += w * tv.y; x2 += w * tv.z; x3 += w * tv.w;
        }
        *(float4*)&cb[h2 * 512 + dt * 128 + dbase] = make_float4(x0, x1, x2, x3);
        __syncthreads();
    }
}

// ---------------- launch ----------------
extern "C" void kernel_launch(void* const* d_in, const int* in_sizes, int n_in,
                              void* d_out, int out_size)
{
    const float* catalog = (const float*)d_in[0];
    const float* neighbors = (const float*)d_in[1];
    const int*   lengths = (const int*)d_in[2];
    const float* W1 = (const float*)d_in[3];
    const float* b1 = (const float*)d_in[4];
    const float* gamma = (const float*)d_in[5];
    const float* beta = (const float*)d_in[6];
    const float* W2 = (const float*)d_in[7];
    const float* b2 = (const float*)d_in[8];
    const float* W3 = (const float*)d_in[9];
    const float* b3 = (const float*)d_in[10];
    const float* Wq = (const float*)d_in[11];
    const float* bq = (const float*)d_in[12];
    const float* Wk = (const float*)d_in[13];
    // d_in[14] = bk: constant shift per (b,h) across n -> cancels in softmax
    const float* Wv = (const float*)d_in[15];
    const float* bv = (const float*)d_in[16];
    const float* Wo = (const float*)d_in[17];
    const float* bo = (const float*)d_in[18];
    float* out = (float*)d_out;

    float *H1, *H2, *emb, *q, *r, *c, *ctx, *WkT, *S, *T;
    cudaGetSymbolAddress((void**)&H1, g_H1);
    cudaGetSymbolAddress((void**)&H2, g_H2);
    cudaGetSymbolAddress((void**)&emb, g_emb);
    cudaGetSymbolAddress((void**)&q, g_q);
    cudaGetSymbolAddress((void**)&r, g_r);
    cudaGetSymbolAddress((void**)&c, g_c);
    cudaGetSymbolAddress((void**)&ctx, g_ctx);
    cudaGetSymbolAddress((void**)&WkT, g_WkT);
    cudaGetSymbolAddress((void**)&S, g_bnS);
    cudaGetSymbolAddress((void**)&T, g_bnT);

    // FFN
    sgemm<true, false><<<dim3(HIDD / BN, Bb / BM), 256>>>(
        catalog, Dd, W1, HIDD, H1, HIDD, b1, nullptr, nullptr, Bb, HIDD, Dd, 1.f);
    bn_stats_kernel<<<HIDD / 256, 256>>>(H1, gamma, beta, S, T);
    sgemm<true, true><<<dim3(HIDD / BN, Bb / BM), 256>>>(
        H1, HIDD, W2, HIDD, H2, HIDD, b2, S, T, Bb, HIDD, HIDD, 1.f);
    sgemm<false, false><<<dim3(Dd / BN, Bb / BM), 256>>>(
        H2, HIDD, W3, Dd, emb, Dd, b3, nullptr, nullptr, Bb, Dd, HIDD, 1.f);

    // q projection
    sgemm<false, false><<<dim3(Dd / BN, Bb / BM), 256>>>(
        emb, Dd, Wq, Dd, q, Dd, bq, nullptr, nullptr, Bb, Dd, Dd, 1.f);

    // r[b,h,d] = (1/8) * sum_j q[b,h,j] * Wk[d, h*64+j]  (via Wk^T)
    transpose512<<<dim3(16, 16), dim3(32, 8)>>>(Wk, WkT);
    for (int h = 0; h < Hh; ++h)
        sgemm<false, false><<<dim3(Dd / BN, Bb / BM), 256>>>(
            q + h * DHh, Dd, WkT + (size_t)h * DHh * Dd, Dd,
            r + h * Dd, Hh * Dd, nullptr, nullptr, nullptr, Bb, Dd, DHh, 0.125f);

    // fused masked softmax attention over neighbors
    cudaFuncSetAttribute(attn_kernel, cudaFuncAttributeMaxDynamicSharedMemorySize,
                         ATTN_SMEM);
    attn_kernel<<<Bb, 256, ATTN_SMEM>>>(neighbors, r, lengths, c);

    // ctx[b, h*64+j] = sum_d c[b,h,d] * Wv[d, h*64+j] + bv[h*64+j]
    for (int h = 0; h < Hh; ++h)
        sgemm<false, false><<<dim3(1, Bb / BM), 256>>>(
            c + h * Dd, Hh * Dd, Wv + h * DHh, Dd,
            ctx + h * DHh, Dd, bv + h * DHh, nullptr, nullptr, Bb, DHh, Dd, 1.f);

    // out = ctx @ Wo + bo
    sgemm<false, false><<<dim3(Dd / BN, Bb / BM), 256>>>(
        ctx, Dd, Wo, Dd, out, Dd, bo, nullptr, nullptr, Bb, Dd, Dd, 1.f);
}

// round 2
// speedup vs baseline: 1.7432x; 1.7432x over previous
#include <cuda_runtime.h>
#include <math.h>

// Problem dims (fixed)
#define Bb   2048
#define Nn   128
#define Dd   512
#define HIDD 2048
#define Hh   8
#define DHh  64

// ---------------- scratch (device globals; no allocations) ----------------
__device__ float g_H1[Bb * HIDD];
__device__ float g_H2[Bb * HIDD];
__device__ float g_emb[Bb * Dd];
__device__ float g_q[Bb * Dd];
__device__ float g_r[Bb * Hh * Dd];
__device__ float g_c[Bb * Hh * Dd];
__device__ float g_ctx[Bb * Dd];
__device__ float g_WkT[Dd * Dd];
__device__ float g_bnS[HIDD];
__device__ float g_bnT[HIDD];

// ---------------- double-buffered fp32 SGEMM ----------------
// C[z][m,n] = scale * sum_k A'[z][m,k] * B[z][k,n] + bias[z][n]
// A' optionally BN-transformed per-k (A*bnS[k]+bnT[k]); optional tanh epilogue.
// Tile TBM x TBN, BK=16, 8x8 per-thread micro-tile, double-buffered smem.
// Requires: M % TBM == 0, N(tile grid) covers exactly, K % 16 == 0.

template <int TBM, int TBN, bool DOTANH, bool DOBN>
__global__ void __launch_bounds__((TBM / 8) * (TBN / 8), 512 / ((TBM / 8) * (TBN / 8)))
sgemm(const float* __restrict__ A, int lda, long sAz,
      const float* __restrict__ B, int ldb, long sBz,
      float* __restrict__ C, int ldc, long sCz,
      const float* __restrict__ bias, long sBiasz,
      const float* __restrict__ bnS, const float* __restrict__ bnT,
      int K, float scale)
{
    constexpr int BK = 16;
    constexpr int THREADS = (TBM / 8) * (TBN / 8);
    constexpr int A_F4 = TBM * BK / 4 / THREADS;
    constexpr int B_F4 = TBN * BK / 4 / THREADS;

    __shared__ float As[2][BK][TBM + 4];
    __shared__ float Bs[2][BK][TBN + 4];

    const int tid = threadIdx.x;
    A += (size_t)blockIdx.z * sAz + (size_t)blockIdx.y * TBM * lda;
    B += (size_t)blockIdx.z * sBz + (size_t)blockIdx.x * TBN;
    C += (size_t)blockIdx.z * sCz + (size_t)blockIdx.y * TBM * ldc
         + (size_t)blockIdx.x * TBN;

    const int tm = (tid / (TBN / 8)) * 8;
    const int tn = (tid % (TBN / 8)) * 8;

    float acc[8][8] = {};
    float4 rA[A_F4], rB[B_F4];

    auto loadG = [&](int k0) {
#pragma unroll
        for (int i = 0; i < A_F4; i++) {
            int idx = tid + i * THREADS;
            int arow = idx / (BK / 4), ak4 = idx % (BK / 4);
            float4 v = *(const float4*)(A + (size_t)arow * lda + k0 + ak4 * 4);
            if (DOBN) {
                float4 s = *(const float4*)(bnS + k0 + ak4 * 4);
                float4 t = *(const float4*)(bnT + k0 + ak4 * 4);
                v.x = fmaf(v.x, s.x, t.x); v.y = fmaf(v.y, s.y, t.y);
                v.z = fmaf(v.z, s.z, t.z); v.w = fmaf(v.w, s.w, t.w);
            }
            rA[i] = v;
        }
#pragma unroll
        for (int i = 0; i < B_F4; i++) {
            int idx = tid + i * THREADS;
            int bk = idx / (TBN / 4), bn4 = idx % (TBN / 4);
            rB[i] = *(const float4*)(B + (size_t)(k0 + bk) * ldb + bn4 * 4);
        }
    };
    auto storeS = [&](int buf) {
#pragma unroll
        for (int i = 0; i < A_F4; i++) {
            int idx = tid + i * THREADS;
            int arow = idx / (BK / 4), ak4 = idx % (BK / 4);
            As[buf][ak4 * 4 + 0][arow] = rA[i].x;
            As[buf][ak4 * 4 + 1][arow] = rA[i].y;
            As[buf][ak4 * 4 + 2][arow] = rA[i].z;
            As[buf][ak4 * 4 + 3][arow] = rA[i].w;
        }
#pragma unroll
        for (int i = 0; i < B_F4; i++) {
            int idx = tid + i * THREADS;
            int bk = idx / (TBN / 4), bn4 = idx % (TBN / 4);
            *(float4*)&Bs[buf][bk][bn4 * 4] = rB[i];
        }
    };

    const int KT = K / BK;
    loadG(0);
    storeS(0);
    __syncthreads();

    for (int kt = 0; kt < KT; ++kt) {
        const int buf = kt & 1;
        if (kt + 1 < KT) loadG((kt + 1) * BK);
#pragma unroll
        for (int kk = 0; kk < BK; ++kk) {
            float4 a0 = *(const float4*)&As[buf][kk][tm];
            float4 a1 = *(const float4*)&As[buf][kk][tm + 4];
            float4 b0 = *(const float4*)&Bs[buf][kk][tn];
            float4 b1 = *(const float4*)&Bs[buf][kk][tn + 4];
            float av[8] = {a0.x, a0.y, a0.z, a0.w, a1.x, a1.y, a1.z, a1.w};
            float bw[8] = {b0.x, b0.y, b0.z, b0.w, b1.x, b1.y, b1.z, b1.w};
#pragma unroll
            for (int i = 0; i < 8; i++)
#pragma unroll
                for (int j = 0; j < 8; j++) acc[i][j] += av[i] * bw[j];
        }
        if (kt + 1 < KT) {
            storeS(buf ^ 1);
            __syncthreads();
        }
    }

    const float* bp = bias ? bias + (size_t)blockIdx.z * sBiasz
                             + (size_t)blockIdx.x * TBN
                           : nullptr;
#pragma unroll
    for (int i = 0; i < 8; i++) {
        float* crow = C + (size_t)(tm + i) * ldc + tn;
#pragma unroll
        for (int j = 0; j < 8; j += 4) {
            float4 v;
            v.x = acc[i][j + 0] * scale + (bp ? bp[tn + j + 0] : 0.f);
            v.y = acc[i][j + 1] * scale + (bp ? bp[tn + j + 1] : 0.f);
            v.z = acc[i][j + 2] * scale + (bp ? bp[tn + j + 2] : 0.f);
            v.w = acc[i][j + 3] * scale + (bp ? bp[tn + j + 3] : 0.f);
            if (DOTANH) {
                v.x = tanhf(v.x); v.y = tanhf(v.y);
                v.z = tanhf(v.z); v.w = tanhf(v.w);
            }
            *(float4*)(crow + j) = v;
        }
    }
}

// ---------------- BatchNorm stats (per-column mean/var over 2048 rows) ----
__global__ void bn_stats_kernel(const float* __restrict__ H1,
                                const float* __restrict__ gamma,
                                const float* __restrict__ beta,
                                float* __restrict__ S, float* __restrict__ T)
{
    int col = blockIdx.x * blockDim.x + threadIdx.x;
    if (col >= HIDD) return;
    double s0 = 0, s1 = 0, s2 = 0, s3 = 0;
    double q0 = 0, q1 = 0, q2 = 0, q3 = 0;
    for (int rr = 0; rr < Bb; rr += 4) {
        float v0 = H1[(size_t)(rr + 0) * HIDD + col];
        float v1 = H1[(size_t)(rr + 1) * HIDD + col];
        float v2 = H1[(size_t)(rr + 2) * HIDD + col];
        float v3 = H1[(size_t)(rr + 3) * HIDD + col];
        s0 += v0; s1 += v1; s2 += v2; s3 += v3;
        q0 += (double)v0 * v0; q1 += (double)v1 * v1;
        q2 += (double)v2 * v2; q3 += (double)v3 * v3;
    }
    double sum = (s0 + s1) + (s2 + s3);
    double sq  = (q0 + q1) + (q2 + q3);
    double mu = sum / 2048.0;
    double var = sq / 2048.0 - mu * mu;
    float rstd = (float)rsqrt(var + 1e-5);
    float sc = gamma[col] * rstd;
    S[col] = sc;
    T[col] = beta[col] - (float)mu * sc;
}

// ---------------- 512x512 transpose (for Wk^T) ----------------
__global__ void transpose512(const float* __restrict__ in, float* __restrict__ out)
{
    __shared__ float t[32][33];
    int bx = blockIdx.x * 32, by = blockIdx.y * 32;
    int x = threadIdx.x, y = threadIdx.y;  // 32x8
#pragma unroll
    for (int i = 0; i < 32; i += 8)
        t[y + i][x] = in[(size_t)(by + y + i) * 512 + bx + x];
    __syncthreads();
#pragma unroll
    for (int i = 0; i < 32; i += 8)
        out[(size_t)(bx + y + i) * 512 + by + x] = t[x][y + i];
}

// ---------------- fused attention over neighbors ----------------
#define TILE_LD 132
#define ATTN_SMEM ((4096 + 1024 + 128 * TILE_LD) * 4)

__global__ __launch_bounds__(256) void attn_kernel(
    const float* __restrict__ nb, const float* __restrict__ r,
    const int* __restrict__ lengths, float* __restrict__ c)
{
    extern __shared__ float sm[];
    float* r_s  = sm;          // [8][512]
    float* sc   = sm + 4096;   // [8][128]
    float* tile = sm + 5120;   // [128][TILE_LD]

    const int b = blockIdx.x;
    const int tid = threadIdx.x;
    const float NEG_INF = __int_as_float(0xff800000u);

    {
        const float4* rg = (const float4*)(r + (size_t)b * 4096);
        float4* rs4 = (float4*)r_s;
        for (int i = tid; i < 1024; i += 256) rs4[i] = rg[i];
        for (int i = tid; i < 1024; i += 256) sc[i] = 0.f;
    }
    __syncthreads();

    const float* nbb = nb + (size_t)b * Nn * Dd;

    // ---- pass 1: scores ----
    for (int dt = 0; dt < 4; ++dt) {
#pragma unroll
        for (int it = 0; it < 16; ++it) {
            int l = tid + it * 256;
            int n = l >> 5, v = l & 31;
            float4 val = *(const float4*)(nbb + (size_t)n * Dd + dt * 128 + v * 4);
            *(float4*)&tile[n * TILE_LD + v * 4] = val;
        }
        __syncthreads();
#pragma unroll
        for (int o = 0; o < 4; ++o) {
            int idx = tid + o * 256;
            int h = idx >> 7, n = idx & 127;
            const float4* rp = (const float4*)(r_s + h * 512 + dt * 128);
            const float4* tp = (const float4*)(tile + n * TILE_LD);
            float a0 = 0, a1 = 0, a2 = 0, a3 = 0;
#pragma unroll
            for (int d4 = 0; d4 < 32; ++d4) {
                float4 tv = tp[d4], rv = rp[d4];
                a0 += tv.x * rv.x; a1 += tv.y * rv.y;
                a2 += tv.z * rv.z; a3 += tv.w * rv.w;
            }
            sc[idx] += (a0 + a1) + (a2 + a3);
        }
        __syncthreads();
    }

    // ---- softmax per head ----
    {
        int w = tid >> 5, lane = tid & 31;
        int len = lengths[b];
        float vals[4];
        float mx = NEG_INF;
#pragma unroll
        for (int kq = 0; kq < 4; kq++) {
            int n = lane + kq * 32;
            float v = (n < len) ? sc[w * 128 + n] : NEG_INF;
            vals[kq] = v;
            mx = fmaxf(mx, v);
        }
#pragma unroll
        for (int off = 16; off; off >>= 1)
            mx = fmaxf(mx, __shfl_xor_sync(0xffffffffu, mx, off));
        float sum = 0.f;
#pragma unroll
        for (int kq = 0; kq < 4; kq++) {
            float e = (vals[kq] == NEG_INF) ? 0.f : expf(vals[kq] - mx);
            vals[kq] = e;
            sum += e;
        }
#pragma unroll
        for (int off = 16; off; off >>= 1)
            sum += __shfl_xor_sync(0xffffffffu, sum, off);
        float inv = 1.f / sum;
#pragma unroll
        for (int kq = 0; kq < 4; kq++)
            sc[w * 128 + lane + kq * 32] = vals[kq] * inv;
    }
    __syncthreads();

    // ---- pass 2: c = attn^T @ nb ----
    float* cb = c + (size_t)b * 4096;
    const int h2 = tid >> 5;
    const int dbase = (tid & 31) * 4;
    for (int dt = 0; dt < 4; ++dt) {
#pragma unroll
        for (int it = 0; it < 16; ++it) {
            int l = tid + it * 256;
            int n = l >> 5, v = l & 31;
            float4 val = *(const float4*)(nbb + (size_t)n * Dd + dt * 128 + v * 4);
            *(float4*)&tile[n * TILE_LD + v * 4] = val;
        }
        __syncthreads();
        float x0 = 0, x1 = 0, x2 = 0, x3 = 0;
        const float* ap = sc + h2 * 128;
#pragma unroll 4
        for (int n = 0; n < 128; ++n) {
            float w = ap[n];
            float4 tv = *(const float4*)&tile[n * TILE_LD + dbase];
            x0 += w * tv.x; x1 += w * tv.y; x2 += w * tv.z; x3 += w * tv.w;
        }
        *(float4*)&cb[h2 * 512 + dt * 128 + dbase] = make_float4(x0, x1, x2, x3);
        __syncthreads();
    }
}

// ---------------- launch ----------------
extern "C" void kernel_launch(void* const* d_in, const int* in_sizes, int n_in,
                              void* d_out, int out_size)
{
    const float* catalog = (const float*)d_in[0];
    const float* neighbors = (const float*)d_in[1];
    const int*   lengths = (const int*)d_in[2];
    const float* W1 = (const float*)d_in[3];
    const float* b1 = (const float*)d_in[4];
    const float* gamma = (const float*)d_in[5];
    const float* beta = (const float*)d_in[6];
    const float* W2 = (const float*)d_in[7];
    const float* b2 = (const float*)d_in[8];
    const float* W3 = (const float*)d_in[9];
    const float* b3 = (const float*)d_in[10];
    const float* Wq = (const float*)d_in[11];
    const float* bq = (const float*)d_in[12];
    const float* Wk = (const float*)d_in[13];
    // d_in[14] = bk: constant per (b,h) across n -> cancels in softmax
    const float* Wv = (const float*)d_in[15];
    const float* bv = (const float*)d_in[16];
    const float* Wo = (const float*)d_in[17];
    const float* bo = (const float*)d_in[18];
    float* out = (float*)d_out;

    float *H1, *H2, *emb, *q, *r, *c, *ctx, *WkT, *S, *T;
    cudaGetSymbolAddress((void**)&H1, g_H1);
    cudaGetSymbolAddress((void**)&H2, g_H2);
    cudaGetSymbolAddress((void**)&emb, g_emb);
    cudaGetSymbolAddress((void**)&q, g_q);
    cudaGetSymbolAddress((void**)&r, g_r);
    cudaGetSymbolAddress((void**)&c, g_c);
    cudaGetSymbolAddress((void**)&ctx, g_ctx);
    cudaGetSymbolAddress((void**)&WkT, g_WkT);
    cudaGetSymbolAddress((void**)&S, g_bnS);
    cudaGetSymbolAddress((void**)&T, g_bnT);

    // ---- FFN ----
    // H1 = tanh(catalog @ W1 + b1): 2048x2048x512
    sgemm<128, 128, true, false><<<dim3(16, 16, 1), 256>>>(
        catalog, Dd, 0, W1, HIDD, 0, H1, HIDD, 0, b1, 0, nullptr, nullptr,
        Dd, 1.f);
    bn_stats_kernel<<<HIDD / 256, 256>>>(H1, gamma, beta, S, T);
    // H2 = tanh(BN(H1) @ W2 + b2): 2048x2048x2048
    sgemm<128, 128, true, true><<<dim3(16, 16, 1), 256>>>(
        H1, HIDD, 0, W2, HIDD, 0, H2, HIDD, 0, b2, 0, S, T, HIDD, 1.f);
    // emb = H2 @ W3 + b3: 2048x512x2048
    sgemm<64, 128, false, false><<<dim3(4, 32, 1), 128>>>(
        H2, HIDD, 0, W3, Dd, 0, emb, Dd, 0, b3, 0, nullptr, nullptr,
        HIDD, 1.f);

    // ---- q projection: 2048x512x512 ----
    sgemm<64, 128, false, false><<<dim3(4, 32, 1), 128>>>(
        emb, Dd, 0, Wq, Dd, 0, q, Dd, 0, bq, 0, nullptr, nullptr, Dd, 1.f);

    // ---- r[b,h,d] = (1/8) * q[b,h,:] @ WkT[h-block]: batched over heads ----
    transpose512<<<dim3(16, 16), dim3(32, 8)>>>(Wk, WkT);
    sgemm<128, 128, false, false><<<dim3(4, 16, 8), 256>>>(
        q, Dd, DHh, WkT, Dd, (long)DHh * Dd, r, Hh * Dd, Dd,
        nullptr, 0, nullptr, nullptr, DHh, 0.125f);

    // ---- fused masked-softmax attention over neighbors ----
    cudaFuncSetAttribute(attn_kernel, cudaFuncAttributeMaxDynamicSharedMemorySize,
                         ATTN_SMEM);
    attn_kernel<<<Bb, 256, ATTN_SMEM>>>(neighbors, r, lengths, c);

    // ---- ctx[b,h*64+j] = c[b,h,:] @ Wv[:,h*64+j] + bv: batched over heads ----
    sgemm<128, 64, false, false><<<dim3(1, 16, 8), 128>>>(
        c, Hh * Dd, Dd, Wv, Dd, DHh, ctx, Dd, DHh, bv, DHh,
        nullptr, nullptr, Dd, 1.f);

    // ---- out = ctx @ Wo + bo: 2048x512x512 ----
    sgemm<64, 128, false, false><<<dim3(4, 32, 1), 128>>>(
        ctx, Dd, 0, Wo, Dd, 0, out, Dd, 0, bo, 0, nullptr, nullptr, Dd, 1.f);
}

// round 4
// speedup vs baseline: 2.2600x; 1.2964x over previous
#include <cuda_runtime.h>
#include <cuda_bf16.h>
#include <math.h>
#include <stdint.h>

// Problem dims (fixed)
#define Bb   2048
#define Nn   128
#define Dd   512
#define HIDD 2048
#define Hh   8
#define DHh  64

// ---------------- scratch (device globals; no allocations) ----------------
__device__ float g_H1[Bb * HIDD];
__device__ float g_H2[Bb * HIDD];
__device__ float g_emb[Bb * Dd];
__device__ float g_q[Bb * Dd];
__device__ float g_r[Bb * Hh * Dd];
__device__ float g_c[Bb * Hh * Dd];
__device__ float g_ctx[Bb * Dd];
__device__ float g_W1T[Dd * HIDD];
__device__ float g_W2T[HIDD * HIDD];
__device__ float g_W3T[HIDD * Dd];
__device__ float g_WqT[Dd * Dd];
__device__ float g_WvT[Dd * Dd];
__device__ float g_WoT[Dd * Dd];
__device__ float g_bnS[HIDD];
__device__ float g_bnT[HIDD];

// ================= warp-MMA helpers (arch-agnostic PTX, no tcgen05) ========
__device__ __forceinline__ uint32_t smem_u32(const void* p) {
    uint32_t a;
    asm("{ .reg .u64 t; cvta.to.shared.u64 t, %1; cvt.u32.u64 %0, t; }"
        : "=r"(a) : "l"(p));
    return a;
}
__device__ __forceinline__ void ldm4(uint32_t* r, uint32_t addr) {
    asm volatile("ldmatrix.sync.aligned.m8n8.x4.shared.b16 {%0,%1,%2,%3}, [%4];"
                 : "=r"(r[0]), "=r"(r[1]), "=r"(r[2]), "=r"(r[3]) : "r"(addr));
}
__device__ __forceinline__ void mma16816(float* c, const uint32_t* a,
                                         const uint32_t* b) {
    asm volatile(
        "mma.sync.aligned.m16n8k16.row.col.f32.bf16.bf16.f32 "
        "{%0,%1,%2,%3}, {%4,%5,%6,%7}, {%8,%9}, {%0,%1,%2,%3};"
        : "+f"(c[0]), "+f"(c[1]), "+f"(c[2]), "+f"(c[3])
        : "r"(a[0]), "r"(a[1]), "r"(a[2]), "r"(a[3]), "r"(b[0]), "r"(b[1]));
}
// split 8 fp32 into bf16 hi / bf16 lo (residual), packed 4x uint32 each
__device__ __forceinline__ void cvt8_bf16x2(float4 v0, float4 v1,
                                            uint4& hh, uint4& ll) {
    float xs[8] = {v0.x, v0.y, v0.z, v0.w, v1.x, v1.y, v1.z, v1.w};
    uint32_t h[4], l[4];
#pragma unroll
    for (int e = 0; e < 4; e++) {
        float a = xs[2 * e], b = xs[2 * e + 1];
        __nv_bfloat162 hb = __floats2bfloat162_rn(a, b);
        float ra = a - __bfloat162float(hb.x);
        float rb = b - __bfloat162float(hb.y);
        __nv_bfloat162 lb = __floats2bfloat162_rn(ra, rb);
        h[e] = *reinterpret_cast<uint32_t*>(&hb);
        l[e] = *reinterpret_cast<uint32_t*>(&lb);
    }
    hh = make_uint4(h[0], h[1], h[2], h[3]);
    ll = make_uint4(l[0], l[1], l[2], l[3]);
}

// ================= bf16x3 tensor-core GEMM via mma.sync =====================
// C[z][m,n] = scale * sum_k A'[z][m,k] * Bt[z][n,k] + bias[z][n]
// A' optionally BN-transformed (A*bnS[k]+bnT[k]); optional tanh epilogue.
// fp32 inputs split to bf16 hi+lo in smem; D = Ah*Bh + Ah*Bl + Al*Bh (fp32 acc).
// CTA tile 128 x TBN, K-tile 32. 256 threads = 8 warps as 2(m) x 4(n).
// smem rows padded to 80B -> conflict-free ldmatrix (r*80 mod 128 permutes).
// Requires M%128==0, N%TBN==0, K%32==0.
template <int TBN, bool DOTANH, bool DOBN>
__global__ void __launch_bounds__(256)
mgemm(const float* __restrict__ A, int lda, long sAz,
      const float* __restrict__ Bt, int ldb, long sBz,
      float* __restrict__ C, int ldc, long sCz,
      const float* __restrict__ bias, long sBiasz,
      const float* __restrict__ bnS, const float* __restrict__ bnT,
      int K, float scale)
{
    constexpr int TBM = 128, TBK = 32;
    constexpr int WN = TBN / 4;      // per-warp n extent
    constexpr int NF = WN / 8;       // n-fragments per warp (2 or 4)
    constexpr int STRIDE = 80;       // bytes per smem row (32 bf16 + 8 pad)

    __shared__ __align__(16) char sAh[TBM * STRIDE];
    __shared__ __align__(16) char sAl[TBM * STRIDE];
    __shared__ __align__(16) char sBh[TBN * STRIDE];
    __shared__ __align__(16) char sBl[TBN * STRIDE];

    const int tid = threadIdx.x, wid = tid >> 5, lane = tid & 31;
    const int wm = wid >> 2, wn = wid & 3;

    A  += (size_t)blockIdx.z * sAz + (size_t)blockIdx.y * TBM * lda;
    Bt += (size_t)blockIdx.z * sBz + (size_t)blockIdx.x * TBN * ldb;
    C  += (size_t)blockIdx.z * sCz + (size_t)blockIdx.y * TBM * ldc
        + (size_t)blockIdx.x * TBN;

    // loaders: thread t -> A row t/2, k-half (t&1)*16 (16 floats)
    const int arow = tid >> 1, akh = (tid & 1) * 16;
    const bool bact = tid < TBN * 2;
    const int brow = tid >> 1, bkh = akh;

    const uint32_t aH = smem_u32(sAh), aL = smem_u32(sAl);
    const uint32_t bH = smem_u32(sBh), bL = smem_u32(sBl);

    // per-lane ldmatrix offsets
    const uint32_t aoff = (uint32_t)(wm * 64 + (lane & 15)) * STRIDE
                        + (uint32_t)((lane >> 4) * 8) * 2;
    const uint32_t boff = (uint32_t)(wn * WN + ((lane >> 4) & 1) * 8 + (lane & 7))
                          * STRIDE
                        + (uint32_t)(((lane >> 3) & 1) * 8) * 2;

    float acc[4][NF][4];
#pragma unroll
    for (int i = 0; i < 4; i++)
#pragma unroll
        for (int j = 0; j < NF; j++)
#pragma unroll
            for (int e = 0; e < 4; e++) acc[i][j][e] = 0.f;

    float4 pa0, pa1, pa2, pa3, pb0, pb1, pb2, pb3;

    auto loadG = [&](int k0) {
        const float* ap = A + (size_t)arow * lda + k0 + akh;
        pa0 = *(const float4*)ap;
        pa1 = *(const float4*)(ap + 4);
        pa2 = *(const float4*)(ap + 8);
        pa3 = *(const float4*)(ap + 12);
        if (DOBN) {
#pragma unroll
            for (int g = 0; g < 4; g++) {
                float4* pv = g == 0 ? &pa0 : g == 1 ? &pa1 : g == 2 ? &pa2 : &pa3;
                float4 s = *(const float4*)(bnS + k0 + akh + g * 4);
                float4 t = *(const float4*)(bnT + k0 + akh + g * 4);
                pv->x = fmaf(pv->x, s.x, t.x); pv->y = fmaf(pv->y, s.y, t.y);
                pv->z = fmaf(pv->z, s.z, t.z); pv->w = fmaf(pv->w, s.w, t.w);
            }
        }
        if (bact) {
            const float* bp = Bt + (size_t)brow * ldb + k0 + bkh;
            pb0 = *(const float4*)bp;
            pb1 = *(const float4*)(bp + 4);
            pb2 = *(const float4*)(bp + 8);
            pb3 = *(const float4*)(bp + 12);
        }
    };
    auto storeS = [&]() {
        uint4 hh, ll;
        uint32_t o = (uint32_t)arow * STRIDE + (uint32_t)akh * 2;
        cvt8_bf16x2(pa0, pa1, hh, ll);
        *(uint4*)(sAh + o) = hh; *(uint4*)(sAl + o) = ll;
        cvt8_bf16x2(pa2, pa3, hh, ll);
        *(uint4*)(sAh + o + 16) = hh; *(uint4*)(sAl + o + 16) = ll;
        if (bact) {
            uint32_t ob = (uint32_t)brow * STRIDE + (uint32_t)bkh * 2;
            cvt8_bf16x2(pb0, pb1, hh, ll);
            *(uint4*)(sBh + ob) = hh; *(uint4*)(sBl + ob) = ll;
            cvt8_bf16x2(pb2, pb3, hh, ll);
            *(uint4*)(sBh + ob + 16) = hh; *(uint4*)(sBl + ob + 16) = ll;
        }
    };

    const int KT = K / TBK;
    loadG(0);
    storeS();
    __syncthreads();

    for (int kt = 0; kt < KT; ++kt) {
        if (kt + 1 < KT) loadG((kt + 1) * TBK);
#pragma unroll
        for (int kh = 0; kh < 2; ++kh) {
            const uint32_t kb = (uint32_t)kh * 32;  // 16 bf16 = 32B
            uint32_t bh[NF][2], bl[NF][2];
#pragma unroll
            for (int p = 0; p < NF / 2; ++p) {
                uint32_t r4[4];
                ldm4(r4, bH + boff + p * 16u * STRIDE + kb);
                bh[2 * p][0] = r4[0]; bh[2 * p][1] = r4[1];
                bh[2 * p + 1][0] = r4[2]; bh[2 * p + 1][1] = r4[3];
                ldm4(r4, bL + boff + p * 16u * STRIDE + kb);
                bl[2 * p][0] = r4[0]; bl[2 * p][1] = r4[1];
                bl[2 * p + 1][0] = r4[2]; bl[2 * p + 1][1] = r4[3];
            }
#pragma unroll
            for (int mf = 0; mf < 4; ++mf) {
                uint32_t ah[4], al[4];
                ldm4(ah, aH + aoff + (uint32_t)mf * 16u * STRIDE + kb);
                ldm4(al, aL + aoff + (uint32_t)mf * 16u * STRIDE + kb);
#pragma unroll
                for (int nf = 0; nf < NF; ++nf) {
                    mma16816(acc[mf][nf], ah, bh[nf]);
                    mma16816(acc[mf][nf], ah, bl[nf]);
                    mma16816(acc[mf][nf], al, bh[nf]);
                }
            }
        }
        __syncthreads();
        if (kt + 1 < KT) {
            storeS();
            __syncthreads();
        }
    }

    // ---- epilogue ----
    const float* bp = bias ? bias + (size_t)blockIdx.z * sBiasz
                           + (size_t)blockIdx.x * TBN
                         : nullptr;
    const int r1 = lane >> 2, c1 = (lane & 3) * 2;
#pragma unroll
    for (int mf = 0; mf < 4; ++mf) {
#pragma unroll
        for (int nf = 0; nf < NF; ++nf) {
            int col = wn * WN + nf * 8 + c1;
            float bx = bp ? bp[col] : 0.f, by = bp ? bp[col + 1] : 0.f;
            int row0 = wm * 64 + mf * 16 + r1;
            float2 v0, v1;
            v0.x = acc[mf][nf][0] * scale + bx;
            v0.y = acc[mf][nf][1] * scale + by;
            v1.x = acc[mf][nf][2] * scale + bx;
            v1.y = acc[mf][nf][3] * scale + by;
            if (DOTANH) {
                v0.x = tanhf(v0.x); v0.y = tanhf(v0.y);
                v1.x = tanhf(v1.x); v1.y = tanhf(v1.y);
            }
            *(float2*)(C + (size_t)row0 * ldc + col) = v0;
            *(float2*)(C + (size_t)(row0 + 8) * ldc + col) = v1;
        }
    }
}

// ---------------- BatchNorm stats (per-column mean/var over 2048 rows) -----
__global__ void bn_stats_kernel(const float* __restrict__ H1,
                                const float* __restrict__ gamma,
                                const float* __restrict__ beta,
                                float* __restrict__ S, float* __restrict__ T)
{
    int col = blockIdx.x * blockDim.x + threadIdx.x;
    if (col >= HIDD) return;
    double s0 = 0, s1 = 0, s2 = 0, s3 = 0;
    double q0 = 0, q1 = 0, q2 = 0, q3 = 0;
    for (int rr = 0; rr < Bb; rr += 4) {
        float v0 = H1[(size_t)(rr + 0) * HIDD + col];
        float v1 = H1[(size_t)(rr + 1) * HIDD + col];
        float v2 = H1[(size_t)(rr + 2) * HIDD + col];
        float v3 = H1[(size_t)(rr + 3) * HIDD + col];
        s0 += v0; s1 += v1; s2 += v2; s3 += v3;
        q0 += (double)v0 * v0; q1 += (double)v1 * v1;
        q2 += (double)v2 * v2; q3 += (double)v3 * v3;
    }
    double sum = (s0 + s1) + (s2 + s3);
    double sq  = (q0 + q1) + (q2 + q3);
    double mu = sum / 2048.0;
    double var = sq / 2048.0 - mu * mu;
    float rstd = (float)rsqrt(var + 1e-5);
    float sc = gamma[col] * rstd;
    S[col] = sc;
    T[col] = beta[col] - (float)mu * sc;
}

// ---------------- generic [R,C] -> [C,R] transpose ----------------
__global__ void transposeK(const float* __restrict__ in, float* __restrict__ out,
                           int R, int C)
{
    __shared__ float t[32][33];
    int bx = blockIdx.x * 32, by = blockIdx.y * 32;
    int x = threadIdx.x, y = threadIdx.y;  // 32x8
#pragma unroll
    for (int i = 0; i < 32; i += 8)
        t[y + i][x] = in[(size_t)(by + y + i) * C + bx + x];
    __syncthreads();
#pragma unroll
    for (int i = 0; i < 32; i += 8)
        out[(size_t)(bx + y + i) * R + by + x] = t[x][y + i];
}

// ---------------- fused attention over neighbors ----------------
#define TILE_LD 132
#define ATTN_SMEM ((4096 + 1024 + 128 * TILE_LD) * 4)

__global__ __launch_bounds__(256) void attn_kernel(
    const float* __restrict__ nb, const float* __restrict__ r,
    const int* __restrict__ lengths, float* __restrict__ c)
{
    extern __shared__ float sm[];
    float* r_s  = sm;          // [8][512]
    float* sc   = sm + 4096;   // [8][128]
    float* tile = sm + 5120;   // [128][TILE_LD]

    const int b = blockIdx.x;
    const int tid = threadIdx.x;
    const float NEG_INF = __int_as_float(0xff800000u);

    {
        const float4* rg = (const float4*)(r + (size_t)b * 4096);
        float4* rs4 = (float4*)r_s;
        for (int i = tid; i < 1024; i += 256) rs4[i] = rg[i];
        for (int i = tid; i < 1024; i += 256) sc[i] = 0.f;
    }
    __syncthreads();

    const float* nbb = nb + (size_t)b * Nn * Dd;

    for (int dt = 0; dt < 4; ++dt) {
#pragma unroll
        for (int it = 0; it < 16; ++it) {
            int l = tid + it * 256;
            int n = l >> 5, v = l & 31;
            float4 val = *(const float4*)(nbb + (size_t)n * Dd + dt * 128 + v * 4);
            *(float4*)&tile[n * TILE_LD + v * 4] = val;
        }
        __syncthreads();
#pragma unroll
        for (int o = 0; o < 4; ++o) {
            int idx = tid + o * 256;
            int h = idx >> 7, n = idx & 127;
            const float4* rp = (const float4*)(r_s + h * 512 + dt * 128);
            const float4* tpv = (const float4*)(tile + n * TILE_LD);
            float a0 = 0, a1 = 0, a2 = 0, a3 = 0;
#pragma unroll
            for (int d4 = 0; d4 < 32; ++d4) {
                float4 tv = tpv[d4], rv = rp[d4];
                a0 += tv.x * rv.x; a1 += tv.y * rv.y;
                a2 += tv.z * rv.z; a3 += tv.w * rv.w;
            }
            sc[idx] += (a0 + a1) + (a2 + a3);
        }
        __syncthreads();
    }

    {
        int w = tid >> 5, lane = tid & 31;
        int len = lengths[b];
        float vals[4];
        float mx = NEG_INF;
#pragma unroll
        for (int kq = 0; kq < 4; kq++) {
            int n = lane + kq * 32;
            float v = (n < len) ? sc[w * 128 + n] : NEG_INF;
            vals[kq] = v;
            mx = fmaxf(mx, v);
        }
#pragma unroll
        for (int off = 16; off; off >>= 1)
            mx = fmaxf(mx, __shfl_xor_sync(0xffffffffu, mx, off));
        float sum = 0.f;
#pragma unroll
        for (int kq = 0; kq < 4; kq++) {
            float e = (vals[kq] == NEG_INF) ? 0.f : expf(vals[kq] - mx);
            vals[kq] = e;
            sum += e;
        }
#pragma unroll
        for (int off = 16; off; off >>= 1)
            sum += __shfl_xor_sync(0xffffffffu, sum, off);
        float inv = 1.f / sum;
#pragma unroll
        for (int kq = 0; kq < 4; kq++)
            sc[w * 128 + lane + kq * 32] = vals[kq] * inv;
    }
    __syncthreads();

    float* cb = c + (size_t)b * 4096;
    const int h2 = tid >> 5;
    const int dbase = (tid & 31) * 4;
    for (int dt = 0; dt < 4; ++dt) {
#pragma unroll
        for (int it = 0; it < 16; ++it) {
            int l = tid + it * 256;
            int n = l >> 5, v = l & 31;
            float4 val = *(const float4*)(nbb + (size_t)n * Dd + dt * 128 + v * 4);
            *(float4*)&tile[n * TILE_LD + v * 4] = val;
        }
        __syncthreads();
        float x0 = 0, x1 = 0, x2 = 0, x3 = 0;
        const float* ap = sc + h2 * 128;
#pragma unroll 4
        for (int n = 0; n < 128; ++n) {
            float w = ap[n];
            float4 tv = *(const float4*)&tile[n * TILE_LD + dbase];
            x0 += w * tv.x; x1 += w * tv.y; x2 += w * tv.z; x3 += w * tv.w;
        }
        *(float4*)&cb[h2 * 512 + dt * 128 + dbase] = make_float4(x0, x1, x2, x3);
        __syncthreads();
    }
}

// ---------------- launch ----------------
extern "C" void kernel_launch(void* const* d_in, const int* in_sizes, int n_in,
                              void* d_out, int out_size)
{
    const float* catalog = (const float*)d_in[0];
    const float* neighbors = (const float*)d_in[1];
    const int*   lengths = (const int*)d_in[2];
    const float* W1 = (const float*)d_in[3];
    const float* b1 = (const float*)d_in[4];
    const float* gamma = (const float*)d_in[5];
    const float* beta = (const float*)d_in[6];
    const float* W2 = (const float*)d_in[7];
    const float* b2 = (const float*)d_in[8];
    const float* W3 = (const float*)d_in[9];
    const float* b3 = (const float*)d_in[10];
    const float* Wq = (const float*)d_in[11];
    const float* bq = (const float*)d_in[12];
    const float* Wk = (const float*)d_in[13];
    // d_in[14] = bk: constant per (b,h) across n -> cancels in softmax
    const float* Wv = (const float*)d_in[15];
    const float* bv = (const float*)d_in[16];
    const float* Wo = (const float*)d_in[17];
    const float* bo = (const float*)d_in[18];
    float* out = (float*)d_out;

    float *H1, *H2, *emb, *q, *r, *c, *ctx;
    float *W1T, *W2T, *W3T, *WqT, *WvT, *WoT, *S, *T;
    cudaGetSymbolAddress((void**)&H1, g_H1);
    cudaGetSymbolAddress((void**)&H2, g_H2);
    cudaGetSymbolAddress((void**)&emb, g_emb);
    cudaGetSymbolAddress((void**)&q, g_q);
    cudaGetSymbolAddress((void**)&r, g_r);
    cudaGetSymbolAddress((void**)&c, g_c);
    cudaGetSymbolAddress((void**)&ctx, g_ctx);
    cudaGetSymbolAddress((void**)&W1T, g_W1T);
    cudaGetSymbolAddress((void**)&W2T, g_W2T);
    cudaGetSymbolAddress((void**)&W3T, g_W3T);
    cudaGetSymbolAddress((void**)&WqT, g_WqT);
    cudaGetSymbolAddress((void**)&WvT, g_WvT);
    cudaGetSymbolAddress((void**)&WoT, g_WoT);
    cudaGetSymbolAddress((void**)&S, g_bnS);
    cudaGetSymbolAddress((void**)&T, g_bnT);

    // ---- weight transposes (Bt = W^T, [N,K] row-major) ----
    transposeK<<<dim3(HIDD / 32, Dd / 32), dim3(32, 8)>>>(W1, W1T, Dd, HIDD);
    transposeK<<<dim3(HIDD / 32, HIDD / 32), dim3(32, 8)>>>(W2, W2T, HIDD, HIDD);
    transposeK<<<dim3(Dd / 32, HIDD / 32), dim3(32, 8)>>>(W3, W3T, HIDD, Dd);
    transposeK<<<dim3(Dd / 32, Dd / 32), dim3(32, 8)>>>(Wq, WqT, Dd, Dd);
    transposeK<<<dim3(Dd / 32, Dd / 32), dim3(32, 8)>>>(Wv, WvT, Dd, Dd);
    transposeK<<<dim3(Dd / 32, Dd / 32), dim3(32, 8)>>>(Wo, WoT, Dd, Dd);

    // ---- FFN ----
    // H1 = tanh(catalog @ W1 + b1): M=2048 N=2048 K=512
    mgemm<128, true, false><<<dim3(16, 16, 1), 256>>>(
        catalog, Dd, 0, W1T, Dd, 0, H1, HIDD, 0, b1, 0, nullptr, nullptr,
        Dd, 1.f);
    bn_stats_kernel<<<HIDD / 256, 256>>>(H1, gamma, beta, S, T);
    // H2 = tanh(BN(H1) @ W2 + b2): 2048x2048x2048
    mgemm<128, true, true><<<dim3(16, 16, 1), 256>>>(
        H1, HIDD, 0, W2T, HIDD, 0, H2, HIDD, 0, b2, 0, S, T, HIDD, 1.f);
    // emb = H2 @ W3 + b3: 2048x512x2048
    mgemm<64, false, false><<<dim3(8, 16, 1), 256>>>(
        H2, HIDD, 0, W3T, HIDD, 0, emb, Dd, 0, b3, 0, nullptr, nullptr,
        HIDD, 1.f);

    // ---- q = emb @ Wq + bq: 2048x512x512 ----
    mgemm<64, false, false><<<dim3(8, 16, 1), 256>>>(
        emb, Dd, 0, WqT, Dd, 0, q, Dd, 0, bq, 0, nullptr, nullptr, Dd, 1.f);

    // ---- r[b,h,d] = (1/8) * sum_j q[b,h,j] * Wk[d, h*64+j] ----
    // B[n=d][k=j] = Wk[d][h*64+j]: Wk rows directly, z-offset 64 columns.
    mgemm<64, false, false><<<dim3(8, 16, 8), 256>>>(
        q, Dd, DHh, Wk, Dd, DHh, r, Hh * Dd, Dd,
        nullptr, 0, nullptr, nullptr, DHh, 0.125f);

    // ---- fused masked-softmax attention over neighbors ----
    cudaFuncSetAttribute(attn_kernel, cudaFuncAttributeMaxDynamicSharedMemorySize,
                         ATTN_SMEM);
    attn_kernel<<<Bb, 256, ATTN_SMEM>>>(neighbors, r, lengths, c);

    // ---- ctx[b, h*64+j] = sum_d c[b,h,d] * Wv[d, h*64+j] + bv ----
    // B[n=j][k=d] = WvT[h*64+j][d]: z-offset 64 rows of WvT.
    mgemm<64, false, false><<<dim3(1, 16, 8), 256>>>(
        c, Hh * Dd, Dd, WvT, Dd, (long)DHh * Dd, ctx, Dd, DHh,
        bv, DHh, nullptr, nullptr, Dd, 1.f);

    // ---- out = ctx @ Wo + bo: 2048x512x512 ----
    mgemm<64, false, false><<<dim3(8, 16, 1), 256>>>(
        ctx, Dd, 0, WoT, Dd, 0, out, Dd, 0, bo, 0, nullptr, nullptr, Dd, 1.f);
}

// round 5
// speedup vs baseline: 2.7831x; 1.2315x over previous
#include <cuda_runtime.h>
#include <cuda_bf16.h>
#include <math.h>
#include <stdint.h>

// Problem dims (fixed)
#define Bb   2048
#define Nn   128
#define Dd   512
#define HIDD 2048
#define Hh   8
#define DHh  64

// ---------------- scratch (device globals; no allocations) ----------------
// split bf16 activations
__device__ __nv_bfloat16 g_cath[Bb * Dd],  g_catl[Bb * Dd];
__device__ __nv_bfloat16 g_H1h[Bb * HIDD], g_H1l[Bb * HIDD];
__device__ __nv_bfloat16 g_H2h[Bb * HIDD], g_H2l[Bb * HIDD];
__device__ __nv_bfloat16 g_embh[Bb * Dd],  g_embl[Bb * Dd];
__device__ __nv_bfloat16 g_qh[Bb * Dd],    g_ql[Bb * Dd];
__device__ __nv_bfloat16 g_ch[Bb * Hh * Dd], g_cl[Bb * Hh * Dd];
__device__ __nv_bfloat16 g_ctxh[Bb * Dd],  g_ctxl[Bb * Dd];
// split bf16 weights (K-major)
__device__ __nv_bfloat16 g_W1Th[HIDD * Dd], g_W1Tl[HIDD * Dd];
__device__ __nv_bfloat16 g_W2h[HIDD * HIDD], g_W2l[HIDD * HIDD];
__device__ __nv_bfloat16 g_W3Th[Dd * HIDD], g_W3Tl[Dd * HIDD];
__device__ __nv_bfloat16 g_WqTh[Dd * Dd],  g_WqTl[Dd * Dd];
__device__ __nv_bfloat16 g_Wkh[Dd * Dd],   g_Wkl[Dd * Dd];
__device__ __nv_bfloat16 g_WvTh[Dd * Dd],  g_WvTl[Dd * Dd];
__device__ __nv_bfloat16 g_WoTh[Dd * Dd],  g_WoTl[Dd * Dd];
// fp32
__device__ float g_r[Bb * Hh * Dd];
__device__ float g_W2T[HIDD * HIDD];
__device__ float g_bnS[HIDD];
__device__ float g_bnT[HIDD];
__device__ float g_bias2[HIDD];

// ================= helpers =================
__device__ __forceinline__ uint32_t smem_u32(const void* p) {
    uint32_t a;
    asm("{ .reg .u64 t; cvta.to.shared.u64 t, %1; cvt.u32.u64 %0, t; }"
        : "=r"(a) : "l"(p));
    return a;
}
__device__ __forceinline__ void cpasync16(uint32_t dst, const void* src) {
    asm volatile("cp.async.cg.shared.global [%0], [%1], 16;"
                 :: "r"(dst), "l"(src) : "memory");
}
__device__ __forceinline__ void cpcommit() {
    asm volatile("cp.async.commit_group;" ::: "memory");
}
template <int N>
__device__ __forceinline__ void cpwait() {
    asm volatile("cp.async.wait_group %0;" :: "n"(N) : "memory");
}
__device__ __forceinline__ void ldm4(uint32_t* r, uint32_t addr) {
    asm volatile("ldmatrix.sync.aligned.m8n8.x4.shared.b16 {%0,%1,%2,%3}, [%4];"
                 : "=r"(r[0]), "=r"(r[1]), "=r"(r[2]), "=r"(r[3]) : "r"(addr));
}
__device__ __forceinline__ void mma16816(float* c, const uint32_t* a,
                                         const uint32_t* b) {
    asm volatile(
        "mma.sync.aligned.m16n8k16.row.col.f32.bf16.bf16.f32 "
        "{%0,%1,%2,%3}, {%4,%5,%6,%7}, {%8,%9}, {%0,%1,%2,%3};"
        : "+f"(c[0]), "+f"(c[1]), "+f"(c[2]), "+f"(c[3])
        : "r"(a[0]), "r"(a[1]), "r"(a[2]), "r"(a[3]), "r"(b[0]), "r"(b[1]));
}
// split a float pair into bf16 hi + bf16 lo and store as packed uint32s
__device__ __forceinline__ void split_store(float x, float y,
                                            __nv_bfloat16* ph,
                                            __nv_bfloat16* pl) {
    __nv_bfloat162 h = __floats2bfloat162_rn(x, y);
    float rx = x - __bfloat162float(h.x);
    float ry = y - __bfloat162float(h.y);
    __nv_bfloat162 l = __floats2bfloat162_rn(rx, ry);
    *reinterpret_cast<uint32_t*>(ph) = *reinterpret_cast<uint32_t*>(&h);
    *reinterpret_cast<uint32_t*>(pl) = *reinterpret_cast<uint32_t*>(&l);
}

// ================= bf16x3 GEMM, pre-split operands, cp.async pipeline ======
// C[z] = scale * A[z] @ B[z]^T + bias[z]; A=(Ah+Al)[M][K], B=(Bh+Bl)[N][K].
// D = Ah*Bh + Ah*Bl + Al*Bh, fp32 accum. CTA tile 128 x TBN, K-tile 32,
// 256 thr = 8 warps (2m x 4n). OUTMODE 0: fp32 C. 1: split bf16 Ch/Cl.
template <int TBN, bool DOTANH, int OUTMODE>
__global__ void __launch_bounds__(256)
bgemm(const __nv_bfloat16* __restrict__ Ah, const __nv_bfloat16* __restrict__ Al,
      int lda, long sAz,
      const __nv_bfloat16* __restrict__ Bh, const __nv_bfloat16* __restrict__ Bl,
      int ldb, long sBz,
      float* __restrict__ C, __nv_bfloat16* __restrict__ Ch,
      __nv_bfloat16* __restrict__ Cl, int ldc, long sCz,
      const float* __restrict__ bias, long sBiasz, int K, float scale)
{
    constexpr int TBM = 128, TBK = 32;
    constexpr int WN = TBN / 4;
    constexpr int NF = WN / 8;
    constexpr int STRIDE = 80;                 // 32 bf16 (64B) + 16B pad
    constexpr int OA_L = TBM * STRIDE;         // 10240
    constexpr int OB_H = 2 * TBM * STRIDE;     // 20480
    constexpr int OB_L = OB_H + TBN * STRIDE;
    constexpr int STAGE = OB_H + 2 * TBN * STRIDE;

    extern __shared__ __align__(16) char dynsm[];
    const uint32_t sb0 = smem_u32(dynsm);

    const int tid = threadIdx.x, wid = tid >> 5, lane = tid & 31;
    const int wm = wid >> 2, wn = wid & 3;

    Ah += (size_t)blockIdx.z * sAz + (size_t)blockIdx.y * TBM * lda;
    Al += (size_t)blockIdx.z * sAz + (size_t)blockIdx.y * TBM * lda;
    Bh += (size_t)blockIdx.z * sBz + (size_t)blockIdx.x * TBN * ldb;
    Bl += (size_t)blockIdx.z * sBz + (size_t)blockIdx.x * TBN * ldb;

    const uint32_t aoff = (uint32_t)(wm * 64 + (lane & 15)) * STRIDE
                        + (uint32_t)((lane >> 4) * 8) * 2;
    const uint32_t boff = (uint32_t)(wn * WN + ((lane >> 4) & 1) * 8 + (lane & 7))
                          * STRIDE
                        + (uint32_t)(((lane >> 3) & 1) * 8) * 2;

    float acc[4][NF][4];
#pragma unroll
    for (int i = 0; i < 4; i++)
#pragma unroll
        for (int j = 0; j < NF; j++)
#pragma unroll
            for (int e = 0; e < 4; e++) acc[i][j][e] = 0.f;

    auto issueStage = [&](int kt, int buf) {
        const uint32_t sb = sb0 + buf * STAGE;
        const int k0 = kt * TBK;
#pragma unroll
        for (int i = 0; i < 2; i++) {            // A: 128 rows x 4 chunks
            int idx = tid + i * 256;
            int r = idx >> 2, cc = idx & 3;
            const size_t go = (size_t)r * lda + k0 + cc * 8;
            const uint32_t so = (uint32_t)r * STRIDE + cc * 16;
            cpasync16(sb + so, Ah + go);
            cpasync16(sb + OA_L + so, Al + go);
        }
#pragma unroll
        for (int i = 0; i < TBN / 64; i++) {     // B: TBN rows x 4 chunks
            int idx = tid + i * 256;
            int r = idx >> 2, cc = idx & 3;
            const size_t go = (size_t)r * ldb + k0 + cc * 8;
            const uint32_t so = (uint32_t)r * STRIDE + cc * 16;
            cpasync16(sb + OB_H + so, Bh + go);
            cpasync16(sb + OB_L + so, Bl + go);
        }
        cpcommit();
    };

    auto compute = [&](int buf) {
        const uint32_t sb = sb0 + buf * STAGE;
#pragma unroll
        for (int kh = 0; kh < 2; ++kh) {
            const uint32_t kb = (uint32_t)kh * 32;
            uint32_t bh[NF][2], bl[NF][2];
#pragma unroll
            for (int p = 0; p < NF / 2; ++p) {
                uint32_t r4[4];
                ldm4(r4, sb + OB_H + boff + p * 16u * STRIDE + kb);
                bh[2 * p][0] = r4[0]; bh[2 * p][1] = r4[1];
                bh[2 * p + 1][0] = r4[2]; bh[2 * p + 1][1] = r4[3];
                ldm4(r4, sb + OB_L + boff + p * 16u * STRIDE + kb);
                bl[2 * p][0] = r4[0]; bl[2 * p][1] = r4[1];
                bl[2 * p + 1][0] = r4[2]; bl[2 * p + 1][1] = r4[3];
            }
#pragma unroll
            for (int mf = 0; mf < 4; ++mf) {
                uint32_t ah[4], al[4];
                ldm4(ah, sb + aoff + (uint32_t)mf * 16u * STRIDE + kb);
                ldm4(al, sb + OA_L + aoff + (uint32_t)mf * 16u * STRIDE + kb);
#pragma unroll
                for (int nf = 0; nf < NF; ++nf) {
                    mma16816(acc[mf][nf], ah, bh[nf]);
                    mma16816(acc[mf][nf], ah, bl[nf]);
                    mma16816(acc[mf][nf], al, bh[nf]);
                }
            }
        }
    };

    const int KT = K / TBK;
    issueStage(0, 0);
    for (int kt = 0; kt < KT; ++kt) {
        if (kt + 1 < KT) {
            issueStage(kt + 1, (kt + 1) & 1);
            cpwait<1>();
        } else {
            cpwait<0>();
        }
        __syncthreads();
        compute(kt & 1);
        __syncthreads();
    }

    // ---- epilogue ----
    const float* bp = bias ? bias + (size_t)blockIdx.z * sBiasz
                           + (size_t)blockIdx.x * TBN
                         : nullptr;
    const size_t cbase = (size_t)blockIdx.z * sCz
                       + (size_t)blockIdx.y * TBM * ldc
                       + (size_t)blockIdx.x * TBN;
    const int r1 = lane >> 2, c1 = (lane & 3) * 2;
#pragma unroll
    for (int mf = 0; mf < 4; ++mf) {
#pragma unroll
        for (int nf = 0; nf < NF; ++nf) {
            int col = wn * WN + nf * 8 + c1;
            float bx = bp ? bp[col] : 0.f, by = bp ? bp[col + 1] : 0.f;
            int row0 = wm * 64 + mf * 16 + r1;
            float2 v0, v1;
            v0.x = acc[mf][nf][0] * scale + bx;
            v0.y = acc[mf][nf][1] * scale + by;
            v1.x = acc[mf][nf][2] * scale + bx;
            v1.y = acc[mf][nf][3] * scale + by;
            if (DOTANH) {
                v0.x = tanhf(v0.x); v0.y = tanhf(v0.y);
                v1.x = tanhf(v1.x); v1.y = tanhf(v1.y);
            }
            size_t o0 = cbase + (size_t)row0 * ldc + col;
            size_t o1 = cbase + (size_t)(row0 + 8) * ldc + col;
            if (OUTMODE == 0) {
                *(float2*)(C + o0) = v0;
                *(float2*)(C + o1) = v1;
            } else {
                split_store(v0.x, v0.y, Ch + o0, Cl + o0);
                split_store(v1.x, v1.y, Ch + o1, Cl + o1);
            }
        }
    }
}

// ---------------- weight prep kernels ----------------
// [R][C] fp32 -> [C][R] bf16 hi/lo
__global__ void transposeSplit(const float* __restrict__ in,
                               __nv_bfloat16* __restrict__ oh,
                               __nv_bfloat16* __restrict__ ol, int R, int C)
{
    __shared__ float t[32][33];
    int bx = blockIdx.x * 32, by = blockIdx.y * 32;
    int x = threadIdx.x, y = threadIdx.y;  // 32x8
#pragma unroll
    for (int i = 0; i < 32; i += 8)
        t[y + i][x] = in[(size_t)(by + y + i) * C + bx + x];
    __syncthreads();
#pragma unroll
    for (int i = 0; i < 32; i += 8) {
        float v = t[x][y + i];
        __nv_bfloat16 h = __float2bfloat16(v);
        size_t o = (size_t)(bx + y + i) * R + by + x;
        oh[o] = h;
        ol[o] = __float2bfloat16(v - __bfloat162float(h));
    }
}
// plain [R][C] fp32 transpose (for W2, scaled later)
__global__ void transposeK(const float* __restrict__ in, float* __restrict__ out,
                           int R, int C)
{
    __shared__ float t[32][33];
    int bx = blockIdx.x * 32, by = blockIdx.y * 32;
    int x = threadIdx.x, y = threadIdx.y;
#pragma unroll
    for (int i = 0; i < 32; i += 8)
        t[y + i][x] = in[(size_t)(by + y + i) * C + bx + x];
    __syncthreads();
#pragma unroll
    for (int i = 0; i < 32; i += 8)
        out[(size_t)(bx + y + i) * R + by + x] = t[x][y + i];
}
// elementwise fp32 -> bf16 hi/lo (n4 float4 groups)
__global__ void splitOnly(const float* __restrict__ in,
                          __nv_bfloat16* __restrict__ oh,
                          __nv_bfloat16* __restrict__ ol, int n4)
{
    int i = blockIdx.x * blockDim.x + threadIdx.x;
    if (i >= n4) return;
    float4 v = ((const float4*)in)[i];
    split_store(v.x, v.y, oh + (size_t)i * 4, ol + (size_t)i * 4);
    split_store(v.z, v.w, oh + (size_t)i * 4 + 2, ol + (size_t)i * 4 + 2);
}

// ---------------- BatchNorm stats from split H1 ----------------
__global__ void bn_stats_kernel(const __nv_bfloat16* __restrict__ H1h,
                                const __nv_bfloat16* __restrict__ H1l,
                                const float* __restrict__ gamma,
                                const float* __restrict__ beta,
                                float* __restrict__ S, float* __restrict__ T)
{
    int col = blockIdx.x * blockDim.x + threadIdx.x;
    if (col >= HIDD) return;
    float s = 0.f;
    double q = 0.0;
    for (int rr = 0; rr < Bb; ++rr) {
        size_t idx = (size_t)rr * HIDD + col;
        float v = __bfloat162float(H1h[idx]) + __bfloat162float(H1l[idx]);
        s += v;
        q += (double)v * v;
    }
    float mu = s / 2048.0f;
    double var = q / 2048.0 - (double)mu * mu;
    float rstd = (float)rsqrt(var + 1e-5);
    float sc = gamma[col] * rstd;
    S[col] = sc;
    T[col] = beta[col] - mu * sc;
}

// ---------------- fold BN into W2: W2hat = S (x) W2T, bias2 = b2 + T @ W2 ----
__global__ void w2prep(const float* __restrict__ W2T, const float* __restrict__ S,
                       const float* __restrict__ T, const float* __restrict__ b2,
                       __nv_bfloat16* __restrict__ W2h,
                       __nv_bfloat16* __restrict__ W2l,
                       float* __restrict__ bias2)
{
    int n = blockIdx.x * 8 + (threadIdx.x >> 5);
    int lane = threadIdx.x & 31;
    const float* row = W2T + (size_t)n * HIDD;
    float tsum = 0.f;
    for (int k = lane * 4; k < HIDD; k += 128) {
        float4 w = *(const float4*)(row + k);
        float4 s = *(const float4*)(S + k);
        float4 t4 = *(const float4*)(T + k);
        tsum += t4.x * w.x + t4.y * w.y + t4.z * w.z + t4.w * w.w;
        size_t o = (size_t)n * HIDD + k;
        split_store(w.x * s.x, w.y * s.y, W2h + o, W2l + o);
        split_store(w.z * s.z, w.w * s.w, W2h + o + 2, W2l + o + 2);
    }
#pragma unroll
    for (int off = 16; off; off >>= 1)
        tsum += __shfl_xor_sync(0xffffffffu, tsum, off);
    if (lane == 0) bias2[n] = b2[n] + tsum;
}

// ---------------- fused attention over neighbors ----------------
#define TILE_LD 132
#define ATTN_SMEM ((4096 + 1024 + 128 * TILE_LD) * 4)

__global__ __launch_bounds__(256) void attn_kernel(
    const float* __restrict__ nb, const float* __restrict__ r,
    const int* __restrict__ lengths,
    __nv_bfloat16* __restrict__ ch, __nv_bfloat16* __restrict__ cl)
{
    extern __shared__ float sm[];
    float* r_s  = sm;          // [8][512]
    float* sc   = sm + 4096;   // [8][128]
    float* tile = sm + 5120;   // [128][TILE_LD]

    const int b = blockIdx.x;
    const int tid = threadIdx.x;
    const float NEG_INF = __int_as_float(0xff800000u);

    {
        const float4* rg = (const float4*)(r + (size_t)b * 4096);
        float4* rs4 = (float4*)r_s;
        for (int i = tid; i < 1024; i += 256) rs4[i] = rg[i];
        for (int i = tid; i < 1024; i += 256) sc[i] = 0.f;
    }
    __syncthreads();

    const float* nbb = nb + (size_t)b * Nn * Dd;

    // ---- pass 1: scores ----
    for (int dt = 0; dt < 4; ++dt) {
#pragma unroll
        for (int it = 0; it < 16; ++it) {
            int l = tid + it * 256;
            int n = l >> 5, v = l & 31;
            float4 val = *(const float4*)(nbb + (size_t)n * Dd + dt * 128 + v * 4);
            *(float4*)&tile[n * TILE_LD + v * 4] = val;
        }
        __syncthreads();
#pragma unroll
        for (int o = 0; o < 4; ++o) {
            int idx = tid + o * 256;
            int h = idx >> 7, n = idx & 127;
            const float4* rp = (const float4*)(r_s + h * 512 + dt * 128);
            const float4* tpv = (const float4*)(tile + n * TILE_LD);
            float a0 = 0, a1 = 0, a2 = 0, a3 = 0;
#pragma unroll
            for (int d4 = 0; d4 < 32; ++d4) {
                float4 tv = tpv[d4], rv = rp[d4];
                a0 += tv.x * rv.x; a1 += tv.y * rv.y;
                a2 += tv.z * rv.z; a3 += tv.w * rv.w;
            }
            sc[idx] += (a0 + a1) + (a2 + a3);
        }
        __syncthreads();
    }

    // ---- softmax per head ----
    {
        int w = tid >> 5, lane = tid & 31;
        int len = lengths[b];
        float vals[4];
        float mx = NEG_INF;
#pragma unroll
        for (int kq = 0; kq < 4; kq++) {
            int n = lane + kq * 32;
            float v = (n < len) ? sc[w * 128 + n] : NEG_INF;
            vals[kq] = v;
            mx = fmaxf(mx, v);
        }
#pragma unroll
        for (int off = 16; off; off >>= 1)
            mx = fmaxf(mx, __shfl_xor_sync(0xffffffffu, mx, off));
        float sum = 0.f;
#pragma unroll
        for (int kq = 0; kq < 4; kq++) {
            float e = (vals[kq] == NEG_INF) ? 0.f : expf(vals[kq] - mx);
            vals[kq] = e;
            sum += e;
        }
#pragma unroll
        for (int off = 16; off; off >>= 1)
            sum += __shfl_xor_sync(0xffffffffu, sum, off);
        float inv = 1.f / sum;
#pragma unroll
        for (int kq = 0; kq < 4; kq++)
            sc[w * 128 + lane + kq * 32] = vals[kq] * inv;
    }
    __syncthreads();

    // ---- pass 2: c = attn^T @ nb (split bf16 output) ----
    __nv_bfloat16* cbh = ch + (size_t)b * 4096;
    __nv_bfloat16* cbl = cl + (size_t)b * 4096;
    const int h2 = tid >> 5;
    const int dbase = (tid & 31) * 4;
    for (int dt = 0; dt < 4; ++dt) {
#pragma unroll
        for (int it = 0; it < 16; ++it) {
            int l = tid + it * 256;
            int n = l >> 5, v = l & 31;
            float4 val = *(const float4*)(nbb + (size_t)n * Dd + dt * 128 + v * 4);
            *(float4*)&tile[n * TILE_LD + v * 4] = val;
        }
        __syncthreads();
        float x0 = 0, x1 = 0, x2 = 0, x3 = 0;
        const float* ap = sc + h2 * 128;
#pragma unroll 4
        for (int n = 0; n < 128; ++n) {
            float w = ap[n];
            float4 tv = *(const float4*)&tile[n * TILE_LD + dbase];
            x0 += w * tv.x; x1 += w * tv.y; x2 += w * tv.z; x3 += w * tv.w;
        }
        int o = h2 * 512 + dt * 128 + dbase;
        split_store(x0, x1, cbh + o, cbl + o);
        split_store(x2, x3, cbh + o + 2, cbl + o + 2);
        __syncthreads();
    }
}

// ---------------- launch ----------------
extern "C" void kernel_launch(void* const* d_in, const int* in_sizes, int n_in,
                              void* d_out, int out_size)
{
    const float* catalog = (const float*)d_in[0];
    const float* neighbors = (const float*)d_in[1];
    const int*   lengths = (const int*)d_in[2];
    const float* W1 = (const float*)d_in[3];
    const float* b1 = (const float*)d_in[4];
    const float* gamma = (const float*)d_in[5];
    const float* beta = (const float*)d_in[6];
    const float* W2 = (const float*)d_in[7];
    const float* b2 = (const float*)d_in[8];
    const float* W3 = (const float*)d_in[9];
    const float* b3 = (const float*)d_in[10];
    const float* Wq = (const float*)d_in[11];
    const float* bq = (const float*)d_in[12];
    const float* Wk = (const float*)d_in[13];
    // d_in[14] = bk: constant per (b,h) across n -> cancels in softmax
    const float* Wv = (const float*)d_in[15];
    const float* bv = (const float*)d_in[16];
    const float* Wo = (const float*)d_in[17];
    const float* bo = (const float*)d_in[18];
    float* out = (float*)d_out;

    __nv_bfloat16 *cath, *catl, *H1h, *H1l, *H2h, *H2l, *embh, *embl;
    __nv_bfloat16 *qh, *ql, *ch, *cl, *ctxh, *ctxl;
    __nv_bfloat16 *W1Th, *W1Tl, *W2h, *W2l, *W3Th, *W3Tl;
    __nv_bfloat16 *WqTh, *WqTl, *Wkh, *Wkl, *WvTh, *WvTl, *WoTh, *WoTl;
    float *r, *W2T, *S, *T, *bias2;
    cudaGetSymbolAddress((void**)&cath, g_cath);
    cudaGetSymbolAddress((void**)&catl, g_catl);
    cudaGetSymbolAddress((void**)&H1h, g_H1h);
    cudaGetSymbolAddress((void**)&H1l, g_H1l);
    cudaGetSymbolAddress((void**)&H2h, g_H2h);
    cudaGetSymbolAddress((void**)&H2l, g_H2l);
    cudaGetSymbolAddress((void**)&embh, g_embh);
    cudaGetSymbolAddress((void**)&embl, g_embl);
    cudaGetSymbolAddress((void**)&qh, g_qh);
    cudaGetSymbolAddress((void**)&ql, g_ql);
    cudaGetSymbolAddress((void**)&ch, g_ch);
    cudaGetSymbolAddress((void**)&cl, g_cl);
    cudaGetSymbolAddress((void**)&ctxh, g_ctxh);
    cudaGetSymbolAddress((void**)&ctxl, g_ctxl);
    cudaGetSymbolAddress((void**)&W1Th, g_W1Th);
    cudaGetSymbolAddress((void**)&W1Tl, g_W1Tl);
    cudaGetSymbolAddress((void**)&W2h, g_W2h);
    cudaGetSymbolAddress((void**)&W2l, g_W2l);
    cudaGetSymbolAddress((void**)&W3Th, g_W3Th);
    cudaGetSymbolAddress((void**)&W3Tl, g_W3Tl);
    cudaGetSymbolAddress((void**)&WqTh, g_WqTh);
    cudaGetSymbolAddress((void**)&WqTl, g_WqTl);
    cudaGetSymbolAddress((void**)&Wkh, g_Wkh);
    cudaGetSymbolAddress((void**)&Wkl, g_Wkl);
    cudaGetSymbolAddress((void**)&WvTh, g_WvTh);
    cudaGetSymbolAddress((void**)&WvTl, g_WvTl);
    cudaGetSymbolAddress((void**)&WoTh, g_WoTh);
    cudaGetSymbolAddress((void**)&WoTl, g_WoTl);
    cudaGetSymbolAddress((void**)&r, g_r);
    cudaGetSymbolAddress((void**)&W2T, g_W2T);
    cudaGetSymbolAddress((void**)&S, g_bnS);
    cudaGetSymbolAddress((void**)&T, g_bnT);
    cudaGetSymbolAddress((void**)&bias2, g_bias2);

    constexpr int SM128 = 2 * (20480 + 2 * 128 * 80);  // 81920
    constexpr int SM64  = 2 * (20480 + 2 * 64 * 80);   // 61440
    cudaFuncSetAttribute(bgemm<128, true, 1>,
                         cudaFuncAttributeMaxDynamicSharedMemorySize, SM128);
    cudaFuncSetAttribute(bgemm<64, false, 1>,
                         cudaFuncAttributeMaxDynamicSharedMemorySize, SM64);
    cudaFuncSetAttribute(bgemm<64, false, 0>,
                         cudaFuncAttributeMaxDynamicSharedMemorySize, SM64);
    cudaFuncSetAttribute(attn_kernel,
                         cudaFuncAttributeMaxDynamicSharedMemorySize, ATTN_SMEM);

    // ---- prep: transpose+split weights, split catalog / Wk ----
    transposeSplit<<<dim3(HIDD / 32, Dd / 32), dim3(32, 8)>>>(W1, W1Th, W1Tl,
                                                              Dd, HIDD);
    transposeK<<<dim3(HIDD / 32, HIDD / 32), dim3(32, 8)>>>(W2, W2T, HIDD, HIDD);
    transposeSplit<<<dim3(Dd / 32, HIDD / 32), dim3(32, 8)>>>(W3, W3Th, W3Tl,
                                                              HIDD, Dd);
    transposeSplit<<<dim3(Dd / 32, Dd / 32), dim3(32, 8)>>>(Wq, WqTh, WqTl,
                                                            Dd, Dd);
    transposeSplit<<<dim3(Dd / 32, Dd / 32), dim3(32, 8)>>>(Wv, WvTh, WvTl,
                                                            Dd, Dd);
    transposeSplit<<<dim3(Dd / 32, Dd / 32), dim3(32, 8)>>>(Wo, WoTh, WoTl,
                                                            Dd, Dd);
    splitOnly<<<(Dd * Dd / 4) / 256, 256>>>(Wk, Wkh, Wkl, Dd * Dd / 4);
    splitOnly<<<(Bb * Dd / 4) / 256, 256>>>(catalog, cath, catl, Bb * Dd / 4);

    // ---- FFN ----
    // H1 = tanh(catalog @ W1 + b1): 2048x2048x512
    bgemm<128, true, 1><<<dim3(16, 16, 1), 256, SM128>>>(
        cath, catl, Dd, 0, W1Th, W1Tl, Dd, 0,
        nullptr, H1h, H1l, HIDD, 0, b1, 0, Dd, 1.f);
    bn_stats_kernel<<<HIDD / 256, 256>>>(H1h, H1l, gamma, beta, S, T);
    w2prep<<<HIDD / 8, 256>>>(W2T, S, T, b2, W2h, W2l, bias2);
    // H2 = tanh(H1 @ (S*W2) + bias2): 2048x2048x2048
    bgemm<128, true, 1><<<dim3(16, 16, 1), 256, SM128>>>(
        H1h, H1l, HIDD, 0, W2h, W2l, HIDD, 0,
        nullptr, H2h, H2l, HIDD, 0, bias2, 0, HIDD, 1.f);
    // emb = H2 @ W3 + b3: 2048x512x2048
    bgemm<64, false, 1><<<dim3(8, 16, 1), 256, SM64>>>(
        H2h, H2l, HIDD, 0, W3Th, W3Tl, HIDD, 0,
        nullptr, embh, embl, Dd, 0, b3, 0, HIDD, 1.f);

    // ---- q = emb @ Wq + bq: 2048x512x512 ----
    bgemm<64, false, 1><<<dim3(8, 16, 1), 256, SM64>>>(
        embh, embl, Dd, 0, WqTh, WqTl, Dd, 0,
        nullptr, qh, ql, Dd, 0, bq, 0, Dd, 1.f);

    // ---- r[b,h,d] = (1/8) * sum_j q[b,h,j] * Wk[d, h*64+j] ----
    bgemm<64, false, 0><<<dim3(8, 16, 8), 256, SM64>>>(
        qh, ql, Dd, DHh, Wkh, Wkl, Dd, DHh,
        r, nullptr, nullptr, Hh * Dd, Dd, nullptr, 0, DHh, 0.125f);

    // ---- fused masked-softmax attention (writes split c) ----
    attn_kernel<<<Bb, 256, ATTN_SMEM>>>(neighbors, r, lengths, ch, cl);

    // ---- ctx[b, h*64+j] = sum_d c[b,h,d] * Wv[d, h*64+j] + bv ----
    bgemm<64, false, 1><<<dim3(1, 16, 8), 256, SM64>>>(
        ch, cl, Hh * Dd, Dd, WvTh, WvTl, Dd, (long)DHh * Dd,
        nullptr, ctxh, ctxl, Dd, DHh, bv, DHh, Dd, 1.f);

    // ---- out = ctx @ Wo + bo: 2048x512x512 ----
    bgemm<64, false, 0><<<dim3(8, 16, 1), 256, SM64>>>(
        ctxh, ctxl, Dd, 0, WoTh, WoTl, Dd, 0,
        out, nullptr, nullptr, Dd, 0, bo, 0, Dd, 1.f);
}

// round 6
// speedup vs baseline: 4.2056x; 1.5111x over previous
#include <cuda_runtime.h>
#include <cuda_bf16.h>
#include <math.h>
#include <stdint.h>

// Problem dims (fixed)
#define Bb   2048
#define Nn   128
#define Dd   512
#define HIDD 2048
#define Hh   8
#define DHh  64

// ---------------- scratch (device globals; no allocations) ----------------
__device__ __nv_bfloat16 g_cath[Bb * Dd],  g_catl[Bb * Dd];
__device__ __nv_bfloat16 g_H1h[Bb * HIDD], g_H1l[Bb * HIDD];
__device__ __nv_bfloat16 g_H2h[Bb * HIDD], g_H2l[Bb * HIDD];
__device__ __nv_bfloat16 g_embh[Bb * Dd],  g_embl[Bb * Dd];
__device__ __nv_bfloat16 g_qh[Bb * Dd],    g_ql[Bb * Dd];
__device__ __nv_bfloat16 g_ch[Bb * Hh * Dd], g_cl[Bb * Hh * Dd];
__device__ __nv_bfloat16 g_ctxh[Bb * Dd],  g_ctxl[Bb * Dd];
__device__ __nv_bfloat16 g_W1Th[HIDD * Dd], g_W1Tl[HIDD * Dd];
__device__ __nv_bfloat16 g_W2h[HIDD * HIDD], g_W2l[HIDD * HIDD];
__device__ __nv_bfloat16 g_W3Th[Dd * HIDD], g_W3Tl[Dd * HIDD];
__device__ __nv_bfloat16 g_WqTh[Dd * Dd],  g_WqTl[Dd * Dd];
__device__ __nv_bfloat16 g_Wkh[Dd * Dd],   g_Wkl[Dd * Dd];
__device__ __nv_bfloat16 g_WvTh[Dd * Dd],  g_WvTl[Dd * Dd];
__device__ __nv_bfloat16 g_WoTh[Dd * Dd],  g_WoTl[Dd * Dd];
__device__ float g_r[Bb * Hh * Dd];
__device__ float g_W2T[HIDD * HIDD];
__device__ float g_bnS[HIDD];
__device__ float g_bnT[HIDD];
__device__ float g_bias2[HIDD];

// ================= helpers =================
__device__ __forceinline__ uint32_t smem_u32(const void* p) {
    uint32_t a;
    asm("{ .reg .u64 t; cvta.to.shared.u64 t, %1; cvt.u32.u64 %0, t; }"
        : "=r"(a) : "l"(p));
    return a;
}
__device__ __forceinline__ void cpasync16(uint32_t dst, const void* src) {
    asm volatile("cp.async.cg.shared.global [%0], [%1], 16;"
                 :: "r"(dst), "l"(src) : "memory");
}
__device__ __forceinline__ void cpcommit() {
    asm volatile("cp.async.commit_group;" ::: "memory");
}
template <int N>
__device__ __forceinline__ void cpwait() {
    asm volatile("cp.async.wait_group %0;" :: "n"(N) : "memory");
}
__device__ __forceinline__ void ldm4(uint32_t* r, uint32_t addr) {
    asm volatile("ldmatrix.sync.aligned.m8n8.x4.shared.b16 {%0,%1,%2,%3}, [%4];"
                 : "=r"(r[0]), "=r"(r[1]), "=r"(r[2]), "=r"(r[3]) : "r"(addr));
}
__device__ __forceinline__ void mma16816(float* c, const uint32_t* a,
                                         const uint32_t* b) {
    asm volatile(
        "mma.sync.aligned.m16n8k16.row.col.f32.bf16.bf16.f32 "
        "{%0,%1,%2,%3}, {%4,%5,%6,%7}, {%8,%9}, {%0,%1,%2,%3};"
        : "+f"(c[0]), "+f"(c[1]), "+f"(c[2]), "+f"(c[3])
        : "r"(a[0]), "r"(a[1]), "r"(a[2]), "r"(a[3]), "r"(b[0]), "r"(b[1]));
}
__device__ __forceinline__ void split_store(float x, float y,
                                            __nv_bfloat16* ph,
                                            __nv_bfloat16* pl) {
    __nv_bfloat162 h = __floats2bfloat162_rn(x, y);
    float rx = x - __bfloat162float(h.x);
    float ry = y - __bfloat162float(h.y);
    __nv_bfloat162 l = __floats2bfloat162_rn(rx, ry);
    *reinterpret_cast<uint32_t*>(ph) = *reinterpret_cast<uint32_t*>(&h);
    *reinterpret_cast<uint32_t*>(pl) = *reinterpret_cast<uint32_t*>(&l);
}

// ================= bf16x3 GEMM, pre-split operands, cp.async pipeline ======
template <int TBN, bool DOTANH, int OUTMODE>
__global__ void __launch_bounds__(256)
bgemm(const __nv_bfloat16* __restrict__ Ah, const __nv_bfloat16* __restrict__ Al,
      int lda, long sAz,
      const __nv_bfloat16* __restrict__ Bh, const __nv_bfloat16* __restrict__ Bl,
      int ldb, long sBz,
      float* __restrict__ C, __nv_bfloat16* __restrict__ Ch,
      __nv_bfloat16* __restrict__ Cl, int ldc, long sCz,
      const float* __restrict__ bias, long sBiasz, int K, float scale)
{
    constexpr int TBM = 128, TBK = 32;
    constexpr int WN = TBN / 4;
    constexpr int NF = WN / 8;
    constexpr int STRIDE = 80;
    constexpr int OA_L = TBM * STRIDE;
    constexpr int OB_H = 2 * TBM * STRIDE;
    constexpr int OB_L = OB_H + TBN * STRIDE;
    constexpr int STAGE = OB_H + 2 * TBN * STRIDE;

    extern __shared__ __align__(16) char dynsm[];
    const uint32_t sb0 = smem_u32(dynsm);

    const int tid = threadIdx.x, wid = tid >> 5, lane = tid & 31;
    const int wm = wid >> 2, wn = wid & 3;

    Ah += (size_t)blockIdx.z * sAz + (size_t)blockIdx.y * TBM * lda;
    Al += (size_t)blockIdx.z * sAz + (size_t)blockIdx.y * TBM * lda;
    Bh += (size_t)blockIdx.z * sBz + (size_t)blockIdx.x * TBN * ldb;
    Bl += (size_t)blockIdx.z * sBz + (size_t)blockIdx.x * TBN * ldb;

    const uint32_t aoff = (uint32_t)(wm * 64 + (lane & 15)) * STRIDE
                        + (uint32_t)((lane >> 4) * 8) * 2;
    const uint32_t boff = (uint32_t)(wn * WN + ((lane >> 4) & 1) * 8 + (lane & 7))
                          * STRIDE
                        + (uint32_t)(((lane >> 3) & 1) * 8) * 2;

    float acc[4][NF][4];
#pragma unroll
    for (int i = 0; i < 4; i++)
#pragma unroll
        for (int j = 0; j < NF; j++)
#pragma unroll
            for (int e = 0; e < 4; e++) acc[i][j][e] = 0.f;

    auto issueStage = [&](int kt, int buf) {
        const uint32_t sb = sb0 + buf * STAGE;
        const int k0 = kt * TBK;
#pragma unroll
        for (int i = 0; i < 2; i++) {
            int idx = tid + i * 256;
            int r = idx >> 2, cc = idx & 3;
            const size_t go = (size_t)r * lda + k0 + cc * 8;
            const uint32_t so = (uint32_t)r * STRIDE + cc * 16;
            cpasync16(sb + so, Ah + go);
            cpasync16(sb + OA_L + so, Al + go);
        }
#pragma unroll
        for (int i = 0; i < TBN / 64; i++) {
            int idx = tid + i * 256;
            int r = idx >> 2, cc = idx & 3;
            const size_t go = (size_t)r * ldb + k0 + cc * 8;
            const uint32_t so = (uint32_t)r * STRIDE + cc * 16;
            cpasync16(sb + OB_H + so, Bh + go);
            cpasync16(sb + OB_L + so, Bl + go);
        }
        cpcommit();
    };

    auto compute = [&](int buf) {
        const uint32_t sb = sb0 + buf * STAGE;
#pragma unroll
        for (int kh = 0; kh < 2; ++kh) {
            const uint32_t kb = (uint32_t)kh * 32;
            uint32_t bh[NF][2], bl[NF][2];
#pragma unroll
            for (int p = 0; p < NF / 2; ++p) {
                uint32_t r4[4];
                ldm4(r4, sb + OB_H + boff + p * 16u * STRIDE + kb);
                bh[2 * p][0] = r4[0]; bh[2 * p][1] = r4[1];
                bh[2 * p + 1][0] = r4[2]; bh[2 * p + 1][1] = r4[3];
                ldm4(r4, sb + OB_L + boff + p * 16u * STRIDE + kb);
                bl[2 * p][0] = r4[0]; bl[2 * p][1] = r4[1];
                bl[2 * p + 1][0] = r4[2]; bl[2 * p + 1][1] = r4[3];
            }
#pragma unroll
            for (int mf = 0; mf < 4; ++mf) {
                uint32_t ah[4], al[4];
                ldm4(ah, sb + aoff + (uint32_t)mf * 16u * STRIDE + kb);
                ldm4(al, sb + OA_L + aoff + (uint32_t)mf * 16u * STRIDE + kb);
#pragma unroll
                for (int nf = 0; nf < NF; ++nf) {
                    mma16816(acc[mf][nf], ah, bh[nf]);
                    mma16816(acc[mf][nf], ah, bl[nf]);
                    mma16816(acc[mf][nf], al, bh[nf]);
                }
            }
        }
    };

    const int KT = K / TBK;
    issueStage(0, 0);
    for (int kt = 0; kt < KT; ++kt) {
        if (kt + 1 < KT) {
            issueStage(kt + 1, (kt + 1) & 1);
            cpwait<1>();
        } else {
            cpwait<0>();
        }
        __syncthreads();
        compute(kt & 1);
        __syncthreads();
    }

    const float* bp = bias ? bias + (size_t)blockIdx.z * sBiasz
                           + (size_t)blockIdx.x * TBN
                         : nullptr;
    const size_t cbase = (size_t)blockIdx.z * sCz
                       + (size_t)blockIdx.y * TBM * ldc
                       + (size_t)blockIdx.x * TBN;
    const int r1 = lane >> 2, c1 = (lane & 3) * 2;
#pragma unroll
    for (int mf = 0; mf < 4; ++mf) {
#pragma unroll
        for (int nf = 0; nf < NF; ++nf) {
            int col = wn * WN + nf * 8 + c1;
            float bx = bp ? bp[col] : 0.f, by = bp ? bp[col + 1] : 0.f;
            int row0 = wm * 64 + mf * 16 + r1;
            float2 v0, v1;
            v0.x = acc[mf][nf][0] * scale + bx;
            v0.y = acc[mf][nf][1] * scale + by;
            v1.x = acc[mf][nf][2] * scale + bx;
            v1.y = acc[mf][nf][3] * scale + by;
            if (DOTANH) {
                v0.x = tanhf(v0.x); v0.y = tanhf(v0.y);
                v1.x = tanhf(v1.x); v1.y = tanhf(v1.y);
            }
            size_t o0 = cbase + (size_t)row0 * ldc + col;
            size_t o1 = cbase + (size_t)(row0 + 8) * ldc + col;
            if (OUTMODE == 0) {
                *(float2*)(C + o0) = v0;
                *(float2*)(C + o1) = v1;
            } else {
                split_store(v0.x, v0.y, Ch + o0, Cl + o0);
                split_store(v1.x, v1.y, Ch + o1, Cl + o1);
            }
        }
    }
}

// ---------------- weight prep kernels ----------------
__global__ void transposeSplit(const float* __restrict__ in,
                               __nv_bfloat16* __restrict__ oh,
                               __nv_bfloat16* __restrict__ ol, int R, int C)
{
    __shared__ float t[32][33];
    int bx = blockIdx.x * 32, by = blockIdx.y * 32;
    int x = threadIdx.x, y = threadIdx.y;
#pragma unroll
    for (int i = 0; i < 32; i += 8)
        t[y + i][x] = in[(size_t)(by + y + i) * C + bx + x];
    __syncthreads();
#pragma unroll
    for (int i = 0; i < 32; i += 8) {
        float v = t[x][y + i];
        __nv_bfloat16 h = __float2bfloat16(v);
        size_t o = (size_t)(bx + y + i) * R + by + x;
        oh[o] = h;
        ol[o] = __float2bfloat16(v - __bfloat162float(h));
    }
}
__global__ void transposeK(const float* __restrict__ in, float* __restrict__ out,
                           int R, int C)
{
    __shared__ float t[32][33];
    int bx = blockIdx.x * 32, by = blockIdx.y * 32;
    int x = threadIdx.x, y = threadIdx.y;
#pragma unroll
    for (int i = 0; i < 32; i += 8)
        t[y + i][x] = in[(size_t)(by + y + i) * C + bx + x];
    __syncthreads();
#pragma unroll
    for (int i = 0; i < 32; i += 8)
        out[(size_t)(bx + y + i) * R + by + x] = t[x][y + i];
}
__global__ void splitOnly(const float* __restrict__ in,
                          __nv_bfloat16* __restrict__ oh,
                          __nv_bfloat16* __restrict__ ol, int n4)
{
    int i = blockIdx.x * blockDim.x + threadIdx.x;
    if (i >= n4) return;
    float4 v = ((const float4*)in)[i];
    split_store(v.x, v.y, oh + (size_t)i * 4, ol + (size_t)i * 4);
    split_store(v.z, v.w, oh + (size_t)i * 4 + 2, ol + (size_t)i * 4 + 2);
}

// ---------------- BatchNorm stats: 128 CTAs, fp32 partials ----------------
__global__ void bn_stats_kernel(const __nv_bfloat16* __restrict__ H1h,
                                const __nv_bfloat16* __restrict__ H1l,
                                const float* __restrict__ gamma,
                                const float* __restrict__ beta,
                                float* __restrict__ S, float* __restrict__ T)
{
    __shared__ float ss[16][16], sq[16][16];
    const int col0 = blockIdx.x * 16;
    const int c = threadIdx.x & 15, rg = threadIdx.x >> 4;
    float s = 0.f, q = 0.f;
#pragma unroll 4
    for (int i = 0; i < 128; ++i) {
        size_t idx = (size_t)(rg * 128 + i) * HIDD + col0 + c;
        float v = __bfloat162float(H1h[idx]) + __bfloat162float(H1l[idx]);
        s += v;
        q += v * v;
    }
    ss[rg][c] = s;
    sq[rg][c] = q;
    __syncthreads();
    if (threadIdx.x < 16) {
        float st = 0.f, qt = 0.f;
#pragma unroll
        for (int g = 0; g < 16; ++g) { st += ss[g][threadIdx.x]; qt += sq[g][threadIdx.x]; }
        float mu = st / 2048.f;
        float var = qt / 2048.f - mu * mu;
        float rstd = rsqrtf(var + 1e-5f);
        float sc = gamma[col0 + threadIdx.x] * rstd;
        S[col0 + threadIdx.x] = sc;
        T[col0 + threadIdx.x] = beta[col0 + threadIdx.x] - mu * sc;
    }
}

// ---------------- fold BN into W2 ----------------
__global__ void w2prep(const float* __restrict__ W2T, const float* __restrict__ S,
                       const float* __restrict__ T, const float* __restrict__ b2,
                       __nv_bfloat16* __restrict__ W2h,
                       __nv_bfloat16* __restrict__ W2l,
                       float* __restrict__ bias2)
{
    int n = blockIdx.x * 8 + (threadIdx.x >> 5);
    int lane = threadIdx.x & 31;
    const float* row = W2T + (size_t)n * HIDD;
    float tsum = 0.f;
    for (int k = lane * 4; k < HIDD; k += 128) {
        float4 w = *(const float4*)(row + k);
        float4 s = *(const float4*)(S + k);
        float4 t4 = *(const float4*)(T + k);
        tsum += t4.x * w.x + t4.y * w.y + t4.z * w.z + t4.w * w.w;
        size_t o = (size_t)n * HIDD + k;
        split_store(w.x * s.x, w.y * s.y, W2h + o, W2l + o);
        split_store(w.z * s.z, w.w * s.w, W2h + o + 2, W2l + o + 2);
    }
#pragma unroll
    for (int off = 16; off; off >>= 1)
        tsum += __shfl_xor_sync(0xffffffffu, tsum, off);
    if (lane == 0) bias2[n] = b2[n] + tsum;
}

// ---------------- fused attention over neighbors (traffic-optimal map) -----
// pass1: each thread covers (n = tid/2, d-half) for ALL 8 heads -> tile read 1x
// pass2: warp w covers n in [16w,16w+16) for all heads, lane = d-seg;
//        8-way partial reduction staged through the (dead) tile region.
#define TILE_LD 132
#define ATTN_SMEM ((4096 + 1024 + 128 * TILE_LD) * 4)

__global__ __launch_bounds__(256) void attn_kernel(
    const float* __restrict__ nb, const float* __restrict__ r,
    const int* __restrict__ lengths,
    __nv_bfloat16* __restrict__ ch, __nv_bfloat16* __restrict__ cl)
{
    extern __shared__ float sm[];
    float* r_s  = sm;          // [8][512]
    float* sc   = sm + 4096;   // [8][128]
    float* tile = sm + 5120;   // [128][TILE_LD] (also reduction scratch)

    const int b = blockIdx.x;
    const int tid = threadIdx.x;
    const float NEG_INF = __int_as_float(0xff800000u);

    {
        const float4* rg = (const float4*)(r + (size_t)b * 4096);
        float4* rs4 = (float4*)r_s;
        for (int i = tid; i < 1024; i += 256) rs4[i] = rg[i];
    }
    __syncthreads();

    const float* nbb = nb + (size_t)b * Nn * Dd;

    // ---- pass 1: scores (tile bytes read once) ----
    const int n1 = tid >> 1, half = tid & 1;
    float part[8] = {0.f, 0.f, 0.f, 0.f, 0.f, 0.f, 0.f, 0.f};
    for (int dt = 0; dt < 4; ++dt) {
#pragma unroll
        for (int it = 0; it < 16; ++it) {
            int l = tid + it * 256;
            int n = l >> 5, v = l & 31;
            float4 val = *(const float4*)(nbb + (size_t)n * Dd + dt * 128 + v * 4);
            *(float4*)&tile[n * TILE_LD + v * 4] = val;
        }
        __syncthreads();
        const float4* trow = (const float4*)(tile + n1 * TILE_LD) + half * 16;
        const float4* rb = (const float4*)r_s + dt * 32 + half * 16;
#pragma unroll
        for (int d4 = 0; d4 < 16; ++d4) {
            float4 tv = trow[d4];
#pragma unroll
            for (int h = 0; h < 8; ++h) {
                float4 rv = rb[h * 128 + d4];
                part[h] += tv.x * rv.x + tv.y * rv.y + tv.z * rv.z + tv.w * rv.w;
            }
        }
        __syncthreads();
    }
#pragma unroll
    for (int h = 0; h < 8; ++h) {
        float o = part[h] + __shfl_xor_sync(0xffffffffu, part[h], 1);
        if (half == 0) sc[h * 128 + n1] = o;
    }
    __syncthreads();

    // ---- softmax per head (warp w = head w) ----
    {
        int w = tid >> 5, lane = tid & 31;
        int len = lengths[b];
        float vals[4];
        float mx = NEG_INF;
#pragma unroll
        for (int kq = 0; kq < 4; kq++) {
            int n = lane + kq * 32;
            float v = (n < len) ? sc[w * 128 + n] : NEG_INF;
            vals[kq] = v;
            mx = fmaxf(mx, v);
        }
#pragma unroll
        for (int off = 16; off; off >>= 1)
            mx = fmaxf(mx, __shfl_xor_sync(0xffffffffu, mx, off));
        float sum = 0.f;
#pragma unroll
        for (int kq = 0; kq < 4; kq++) {
            float e = (vals[kq] == NEG_INF) ? 0.f : expf(vals[kq] - mx);
            vals[kq] = e;
            sum += e;
        }
#pragma unroll
        for (int off = 16; off; off >>= 1)
            sum += __shfl_xor_sync(0xffffffffu, sum, off);
        float inv = 1.f / sum;
#pragma unroll
        for (int kq = 0; kq < 4; kq++)
            sc[w * 128 + lane + kq * 32] = vals[kq] * inv;
    }
    __syncthreads();

    // ---- pass 2: c = attn^T @ nb (tile read once, staged reduction) ----
    __nv_bfloat16* cbh = ch + (size_t)b * 4096;
    __nv_bfloat16* cbl = cl + (size_t)b * 4096;
    const int wpart = tid >> 5;      // warp = n-part (16 rows)
    const int seg = tid & 31;        // lane = d-seg (float4)
    float4* scratch = (float4*)tile;
    for (int dt = 0; dt < 4; ++dt) {
#pragma unroll
        for (int it = 0; it < 16; ++it) {
            int l = tid + it * 256;
            int n = l >> 5, v = l & 31;
            float4 val = *(const float4*)(nbb + (size_t)n * Dd + dt * 128 + v * 4);
            *(float4*)&tile[n * TILE_LD + v * 4] = val;
        }
        __syncthreads();
        float4 a[8];
#pragma unroll
        for (int h = 0; h < 8; ++h) a[h] = make_float4(0.f, 0.f, 0.f, 0.f);
#pragma unroll
        for (int ni = 0; ni < 16; ++ni) {
            int n = wpart * 16 + ni;
            float4 tv = *((const float4*)(tile + n * TILE_LD) + seg);
#pragma unroll
            for (int h = 0; h < 8; ++h) {
                float w = sc[h * 128 + n];
                a[h].x += w * tv.x; a[h].y += w * tv.y;
                a[h].z += w * tv.z; a[h].w += w * tv.w;
            }
        }
        __syncthreads();  // done reading tile; reuse as scratch
#pragma unroll
        for (int h = 0; h < 8; ++h)
            scratch[(wpart * 8 + h) * 32 + seg] = a[h];
        __syncthreads();
        {
            const int h2 = tid >> 5;  // now warp = head
            float4 s4 = scratch[h2 * 32 + seg];
#pragma unroll
            for (int p = 1; p < 8; ++p) {
                float4 t4 = scratch[(p * 8 + h2) * 32 + seg];
                s4.x += t4.x; s4.y += t4.y; s4.z += t4.z; s4.w += t4.w;
            }
            int o = h2 * 512 + dt * 128 + seg * 4;
            split_store(s4.x, s4.y, cbh + o, cbl + o);
            split_store(s4.z, s4.w, cbh + o + 2, cbl + o + 2);
        }
        __syncthreads();
    }
}

// ---------------- launch ----------------
extern "C" void kernel_launch(void* const* d_in, const int* in_sizes, int n_in,
                              void* d_out, int out_size)
{
    const float* catalog = (const float*)d_in[0];
    const float* neighbors = (const float*)d_in[1];
    const int*   lengths = (const int*)d_in[2];
    const float* W1 = (const float*)d_in[3];
    const float* b1 = (const float*)d_in[4];
    const float* gamma = (const float*)d_in[5];
    const float* beta = (const float*)d_in[6];
    const float* W2 = (const float*)d_in[7];
    const float* b2 = (const float*)d_in[8];
    const float* W3 = (const float*)d_in[9];
    const float* b3 = (const float*)d_in[10];
    const float* Wq = (const float*)d_in[11];
    const float* bq = (const float*)d_in[12];
    const float* Wk = (const float*)d_in[13];
    // d_in[14] = bk: constant per (b,h) across n -> cancels in softmax
    const float* Wv = (const float*)d_in[15];
    const float* bv = (const float*)d_in[16];
    const float* Wo = (const float*)d_in[17];
    const float* bo = (const float*)d_in[18];
    float* out = (float*)d_out;

    __nv_bfloat16 *cath, *catl, *H1h, *H1l, *H2h, *H2l, *embh, *embl;
    __nv_bfloat16 *qh, *ql, *ch, *cl, *ctxh, *ctxl;
    __nv_bfloat16 *W1Th, *W1Tl, *W2h, *W2l, *W3Th, *W3Tl;
    __nv_bfloat16 *WqTh, *WqTl, *Wkh, *Wkl, *WvTh, *WvTl, *WoTh, *WoTl;
    float *r, *W2T, *S, *T, *bias2;
    cudaGetSymbolAddress((void**)&cath, g_cath);
    cudaGetSymbolAddress((void**)&catl, g_catl);
    cudaGetSymbolAddress((void**)&H1h, g_H1h);
    cudaGetSymbolAddress((void**)&H1l, g_H1l);
    cudaGetSymbolAddress((void**)&H2h, g_H2h);
    cudaGetSymbolAddress((void**)&H2l, g_H2l);
    cudaGetSymbolAddress((void**)&embh, g_embh);
    cudaGetSymbolAddress((void**)&embl, g_embl);
    cudaGetSymbolAddress((void**)&qh, g_qh);
    cudaGetSymbolAddress((void**)&ql, g_ql);
    cudaGetSymbolAddress((void**)&ch, g_ch);
    cudaGetSymbolAddress((void**)&cl, g_cl);
    cudaGetSymbolAddress((void**)&ctxh, g_ctxh);
    cudaGetSymbolAddress((void**)&ctxl, g_ctxl);
    cudaGetSymbolAddress((void**)&W1Th, g_W1Th);
    cudaGetSymbolAddress((void**)&W1Tl, g_W1Tl);
    cudaGetSymbolAddress((void**)&W2h, g_W2h);
    cudaGetSymbolAddress((void**)&W2l, g_W2l);
    cudaGetSymbolAddress((void**)&W3Th, g_W3Th);
    cudaGetSymbolAddress((void**)&W3Tl, g_W3Tl);
    cudaGetSymbolAddress((void**)&WqTh, g_WqTh);
    cudaGetSymbolAddress((void**)&WqTl, g_WqTl);
    cudaGetSymbolAddress((void**)&Wkh, g_Wkh);
    cudaGetSymbolAddress((void**)&Wkl, g_Wkl);
    cudaGetSymbolAddress((void**)&WvTh, g_WvTh);
    cudaGetSymbolAddress((void**)&WvTl, g_WvTl);
    cudaGetSymbolAddress((void**)&WoTh, g_WoTh);
    cudaGetSymbolAddress((void**)&WoTl, g_WoTl);
    cudaGetSymbolAddress((void**)&r, g_r);
    cudaGetSymbolAddress((void**)&W2T, g_W2T);
    cudaGetSymbolAddress((void**)&S, g_bnS);
    cudaGetSymbolAddress((void**)&T, g_bnT);
    cudaGetSymbolAddress((void**)&bias2, g_bias2);

    constexpr int SM128 = 2 * (20480 + 2 * 128 * 80);  // 81920
    constexpr int SM64  = 2 * (20480 + 2 * 64 * 80);   // 61440
    cudaFuncSetAttribute(bgemm<128, true, 1>,
                         cudaFuncAttributeMaxDynamicSharedMemorySize, SM128);
    cudaFuncSetAttribute(bgemm<64, false, 1>,
                         cudaFuncAttributeMaxDynamicSharedMemorySize, SM64);
    cudaFuncSetAttribute(bgemm<64, false, 0>,
                         cudaFuncAttributeMaxDynamicSharedMemorySize, SM64);
    cudaFuncSetAttribute(attn_kernel,
                         cudaFuncAttributeMaxDynamicSharedMemorySize, ATTN_SMEM);

    // ---- prep ----
    transposeSplit<<<dim3(HIDD / 32, Dd / 32), dim3(32, 8)>>>(W1, W1Th, W1Tl,
                                                              Dd, HIDD);
    transposeK<<<dim3(HIDD / 32, HIDD / 32), dim3(32, 8)>>>(W2, W2T, HIDD, HIDD);
    transposeSplit<<<dim3(Dd / 32, HIDD / 32), dim3(32, 8)>>>(W3, W3Th, W3Tl,
                                                              HIDD, Dd);
    transposeSplit<<<dim3(Dd / 32, Dd / 32), dim3(32, 8)>>>(Wq, WqTh, WqTl,
                                                            Dd, Dd);
    transposeSplit<<<dim3(Dd / 32, Dd / 32), dim3(32, 8)>>>(Wv, WvTh, WvTl,
                                                            Dd, Dd);
    transposeSplit<<<dim3(Dd / 32, Dd / 32), dim3(32, 8)>>>(Wo, WoTh, WoTl,
                                                            Dd, Dd);
    splitOnly<<<(Dd * Dd / 4) / 256, 256>>>(Wk, Wkh, Wkl, Dd * Dd / 4);
    splitOnly<<<(Bb * Dd / 4) / 256, 256>>>(catalog, cath, catl, Bb * Dd / 4);

    // ---- FFN ----
    bgemm<128, true, 1><<<dim3(16, 16, 1), 256, SM128>>>(
        cath, catl, Dd, 0, W1Th, W1Tl, Dd, 0,
        nullptr, H1h, H1l, HIDD, 0, b1, 0, Dd, 1.f);
    bn_stats_kernel<<<HIDD / 16, 256>>>(H1h, H1l, gamma, beta, S, T);
    w2prep<<<HIDD / 8, 256>>>(W2T, S, T, b2, W2h, W2l, bias2);
    bgemm<128, true, 1><<<dim3(16, 16, 1), 256, SM128>>>(
        H1h, H1l, HIDD, 0, W2h, W2l, HIDD, 0,
        nullptr, H2h, H2l, HIDD, 0, bias2, 0, HIDD, 1.f);
    bgemm<64, false, 1><<<dim3(8, 16, 1), 256, SM64>>>(
        H2h, H2l, HIDD, 0, W3Th, W3Tl, HIDD, 0,
        nullptr, embh, embl, Dd, 0, b3, 0, HIDD, 1.f);

    // ---- q = emb @ Wq + bq ----
    bgemm<64, false, 1><<<dim3(8, 16, 1), 256, SM64>>>(
        embh, embl, Dd, 0, WqTh, WqTl, Dd, 0,
        nullptr, qh, ql, Dd, 0, bq, 0, Dd, 1.f);

    // ---- r[b,h,d] = (1/8) * sum_j q[b,h,j] * Wk[d, h*64+j] ----
    bgemm<64, false, 0><<<dim3(8, 16, 8), 256, SM64>>>(
        qh, ql, Dd, DHh, Wkh, Wkl, Dd, DHh,
        r, nullptr, nullptr, Hh * Dd, Dd, nullptr, 0, DHh, 0.125f);

    // ---- fused masked-softmax attention (writes split c) ----
    attn_kernel<<<Bb, 256, ATTN_SMEM>>>(neighbors, r, lengths, ch, cl);

    // ---- ctx = c @ Wv + bv (per head) ----
    bgemm<64, false, 1><<<dim3(1, 16, 8), 256, SM64>>>(
        ch, cl, Hh * Dd, Dd, WvTh, WvTl, Dd, (long)DHh * Dd,
        nullptr, ctxh, ctxl, Dd, DHh, bv, DHh, Dd, 1.f);

    // ---- out = ctx @ Wo + bo ----
    bgemm<64, false, 0><<<dim3(8, 16, 1), 256, SM64>>>(
        ctxh, ctxl, Dd, 0, WoTh, WoTl, Dd, 0,
        out, nullptr, nullptr, Dd, 0, bo, 0, Dd, 1.f);
}

// round 7
// speedup vs baseline: 4.6323x; 1.1015x over previous
#include <cuda_runtime.h>
#include <cuda_bf16.h>
#include <math.h>
#include <stdint.h>

// Problem dims (fixed)
#define Bb   2048
#define Nn   128
#define Dd   512
#define HIDD 2048
#define Hh   8
#define DHh  64

// ---------------- scratch (device globals; no allocations) ----------------
__device__ __nv_bfloat16 g_cath[Bb * Dd],  g_catl[Bb * Dd];
__device__ __nv_bfloat16 g_H1h[Bb * HIDD], g_H1l[Bb * HIDD];
__device__ __nv_bfloat16 g_H2h[Bb * HIDD], g_H2l[Bb * HIDD];
__device__ __nv_bfloat16 g_embh[Bb * Dd],  g_embl[Bb * Dd];
__device__ __nv_bfloat16 g_qh[Bb * Dd],    g_ql[Bb * Dd];
__device__ __nv_bfloat16 g_ch[Bb * Hh * Dd], g_cl[Bb * Hh * Dd];
__device__ __nv_bfloat16 g_ctxh[Bb * Dd],  g_ctxl[Bb * Dd];
__device__ __nv_bfloat16 g_W1Th[HIDD * Dd], g_W1Tl[HIDD * Dd];
__device__ __nv_bfloat16 g_W2h[HIDD * HIDD], g_W2l[HIDD * HIDD];
__device__ __nv_bfloat16 g_W3Th[Dd * HIDD], g_W3Tl[Dd * HIDD];
__device__ __nv_bfloat16 g_WqTh[Dd * Dd],  g_WqTl[Dd * Dd];
__device__ __nv_bfloat16 g_Wkh[Dd * Dd],   g_Wkl[Dd * Dd];
__device__ __nv_bfloat16 g_WvTh[Dd * Dd],  g_WvTl[Dd * Dd];
__device__ __nv_bfloat16 g_WoTh[Dd * Dd],  g_WoTl[Dd * Dd];
__device__ float g_r[Bb * Hh * Dd];
__device__ float g_W2T[HIDD * HIDD];
__device__ float g_bnS[HIDD];
__device__ float g_bnT[HIDD];
__device__ float g_bias2[HIDD];

// ================= helpers =================
__device__ __forceinline__ uint32_t smem_u32(const void* p) {
    uint32_t a;
    asm("{ .reg .u64 t; cvta.to.shared.u64 t, %1; cvt.u32.u64 %0, t; }"
        : "=r"(a) : "l"(p));
    return a;
}
__device__ __forceinline__ void cpasync16(uint32_t dst, const void* src) {
    asm volatile("cp.async.cg.shared.global [%0], [%1], 16;"
                 :: "r"(dst), "l"(src) : "memory");
}
__device__ __forceinline__ void cpcommit() {
    asm volatile("cp.async.commit_group;" ::: "memory");
}
template <int N>
__device__ __forceinline__ void cpwait() {
    asm volatile("cp.async.wait_group %0;" :: "n"(N) : "memory");
}
__device__ __forceinline__ void ldm4(uint32_t* r, uint32_t addr) {
    asm volatile("ldmatrix.sync.aligned.m8n8.x4.shared.b16 {%0,%1,%2,%3}, [%4];"
                 : "=r"(r[0]), "=r"(r[1]), "=r"(r[2]), "=r"(r[3]) : "r"(addr));
}
__device__ __forceinline__ void mma16816(float* c, const uint32_t* a,
                                         const uint32_t* b) {
    asm volatile(
        "mma.sync.aligned.m16n8k16.row.col.f32.bf16.bf16.f32 "
        "{%0,%1,%2,%3}, {%4,%5,%6,%7}, {%8,%9}, {%0,%1,%2,%3};"
        : "+f"(c[0]), "+f"(c[1]), "+f"(c[2]), "+f"(c[3])
        : "r"(a[0]), "r"(a[1]), "r"(a[2]), "r"(a[3]), "r"(b[0]), "r"(b[1]));
}
__device__ __forceinline__ void split_store(float x, float y,
                                            __nv_bfloat16* ph,
                                            __nv_bfloat16* pl) {
    __nv_bfloat162 h = __floats2bfloat162_rn(x, y);
    float rx = x - __bfloat162float(h.x);
    float ry = y - __bfloat162float(h.y);
    __nv_bfloat162 l = __floats2bfloat162_rn(rx, ry);
    *reinterpret_cast<uint32_t*>(ph) = *reinterpret_cast<uint32_t*>(&h);
    *reinterpret_cast<uint32_t*>(pl) = *reinterpret_cast<uint32_t*>(&l);
}

// ================= bf16x3 GEMM, 3-stage cp.async, 1 sync/iter ==============
template <int TBN, bool DOTANH, int OUTMODE>
__global__ void __launch_bounds__(256)
bgemm(const __nv_bfloat16* __restrict__ Ah, const __nv_bfloat16* __restrict__ Al,
      int lda, long sAz,
      const __nv_bfloat16* __restrict__ Bh, const __nv_bfloat16* __restrict__ Bl,
      int ldb, long sBz,
      float* __restrict__ C, __nv_bfloat16* __restrict__ Ch,
      __nv_bfloat16* __restrict__ Cl, int ldc, long sCz,
      const float* __restrict__ bias, long sBiasz, int K, float scale)
{
    constexpr int TBM = 128, TBK = 32;
    constexpr int WN = TBN / 4;
    constexpr int NF = WN / 8;
    constexpr int STRIDE = 80;
    constexpr int OA_L = TBM * STRIDE;
    constexpr int OB_H = 2 * TBM * STRIDE;
    constexpr int OB_L = OB_H + TBN * STRIDE;
    constexpr int STAGE = OB_H + 2 * TBN * STRIDE;

    extern __shared__ __align__(16) char dynsm[];
    const uint32_t sb0 = smem_u32(dynsm);

    const int tid = threadIdx.x, wid = tid >> 5, lane = tid & 31;
    const int wm = wid >> 2, wn = wid & 3;

    Ah += (size_t)blockIdx.z * sAz + (size_t)blockIdx.y * TBM * lda;
    Al += (size_t)blockIdx.z * sAz + (size_t)blockIdx.y * TBM * lda;
    Bh += (size_t)blockIdx.z * sBz + (size_t)blockIdx.x * TBN * ldb;
    Bl += (size_t)blockIdx.z * sBz + (size_t)blockIdx.x * TBN * ldb;

    const uint32_t aoff = (uint32_t)(wm * 64 + (lane & 15)) * STRIDE
                        + (uint32_t)((lane >> 4) * 8) * 2;
    const uint32_t boff = (uint32_t)(wn * WN + ((lane >> 4) & 1) * 8 + (lane & 7))
                          * STRIDE
                        + (uint32_t)(((lane >> 3) & 1) * 8) * 2;

    float acc[4][NF][4];
#pragma unroll
    for (int i = 0; i < 4; i++)
#pragma unroll
        for (int j = 0; j < NF; j++)
#pragma unroll
            for (int e = 0; e < 4; e++) acc[i][j][e] = 0.f;

    auto issueStage = [&](int kt, int buf) {
        const uint32_t sb = sb0 + buf * STAGE;
        const int k0 = kt * TBK;
#pragma unroll
        for (int i = 0; i < 2; i++) {
            int idx = tid + i * 256;
            int r = idx >> 2, cc = idx & 3;
            const size_t go = (size_t)r * lda + k0 + cc * 8;
            const uint32_t so = (uint32_t)r * STRIDE + cc * 16;
            cpasync16(sb + so, Ah + go);
            cpasync16(sb + OA_L + so, Al + go);
        }
#pragma unroll
        for (int i = 0; i < TBN / 64; i++) {
            int idx = tid + i * 256;
            int r = idx >> 2, cc = idx & 3;
            const size_t go = (size_t)r * ldb + k0 + cc * 8;
            const uint32_t so = (uint32_t)r * STRIDE + cc * 16;
            cpasync16(sb + OB_H + so, Bh + go);
            cpasync16(sb + OB_L + so, Bl + go);
        }
        cpcommit();
    };

    auto compute = [&](int buf) {
        const uint32_t sb = sb0 + buf * STAGE;
#pragma unroll
        for (int kh = 0; kh < 2; ++kh) {
            const uint32_t kb = (uint32_t)kh * 32;
            uint32_t bh[NF][2], bl[NF][2];
#pragma unroll
            for (int p = 0; p < NF / 2; ++p) {
                uint32_t r4[4];
                ldm4(r4, sb + OB_H + boff + p * 16u * STRIDE + kb);
                bh[2 * p][0] = r4[0]; bh[2 * p][1] = r4[1];
                bh[2 * p + 1][0] = r4[2]; bh[2 * p + 1][1] = r4[3];
                ldm4(r4, sb + OB_L + boff + p * 16u * STRIDE + kb);
                bl[2 * p][0] = r4[0]; bl[2 * p][1] = r4[1];
                bl[2 * p + 1][0] = r4[2]; bl[2 * p + 1][1] = r4[3];
            }
#pragma unroll
            for (int mf = 0; mf < 4; ++mf) {
                uint32_t ah[4], al[4];
                ldm4(ah, sb + aoff + (uint32_t)mf * 16u * STRIDE + kb);
                ldm4(al, sb + OA_L + aoff + (uint32_t)mf * 16u * STRIDE + kb);
#pragma unroll
                for (int nf = 0; nf < NF; ++nf) {
                    mma16816(acc[mf][nf], ah, bh[nf]);
                    mma16816(acc[mf][nf], ah, bl[nf]);
                    mma16816(acc[mf][nf], al, bh[nf]);
                }
            }
        }
    };

    const int KT = K / TBK;
    issueStage(0, 0);
    if (KT > 1) issueStage(1, 1);
    for (int kt = 0; kt < KT; ++kt) {
        if (kt + 1 < KT) cpwait<1>(); else cpwait<0>();
        __syncthreads();
        if (kt + 2 < KT) issueStage(kt + 2, (kt + 2) % 3);
        compute(kt % 3);
    }

    const float* bp = bias ? bias + (size_t)blockIdx.z * sBiasz
                           + (size_t)blockIdx.x * TBN
                         : nullptr;
    const size_t cbase = (size_t)blockIdx.z * sCz
                       + (size_t)blockIdx.y * TBM * ldc
                       + (size_t)blockIdx.x * TBN;
    const int r1 = lane >> 2, c1 = (lane & 3) * 2;
#pragma unroll
    for (int mf = 0; mf < 4; ++mf) {
#pragma unroll
        for (int nf = 0; nf < NF; ++nf) {
            int col = wn * WN + nf * 8 + c1;
            float bx = bp ? bp[col] : 0.f, by = bp ? bp[col + 1] : 0.f;
            int row0 = wm * 64 + mf * 16 + r1;
            float2 v0, v1;
            v0.x = acc[mf][nf][0] * scale + bx;
            v0.y = acc[mf][nf][1] * scale + by;
            v1.x = acc[mf][nf][2] * scale + bx;
            v1.y = acc[mf][nf][3] * scale + by;
            if (DOTANH) {
                v0.x = tanhf(v0.x); v0.y = tanhf(v0.y);
                v1.x = tanhf(v1.x); v1.y = tanhf(v1.y);
            }
            size_t o0 = cbase + (size_t)row0 * ldc + col;
            size_t o1 = cbase + (size_t)(row0 + 8) * ldc + col;
            if (OUTMODE == 0) {
                *(float2*)(C + o0) = v0;
                *(float2*)(C + o1) = v1;
            } else {
                split_store(v0.x, v0.y, Ch + o0, Cl + o0);
                split_store(v1.x, v1.y, Ch + o1, Cl + o1);
            }
        }
    }
}

// ---------------- weight prep kernels ----------------
__global__ void transposeSplit(const float* __restrict__ in,
                               __nv_bfloat16* __restrict__ oh,
                               __nv_bfloat16* __restrict__ ol, int R, int C)
{
    __shared__ float t[32][33];
    int bx = blockIdx.x * 32, by = blockIdx.y * 32;
    int x = threadIdx.x, y = threadIdx.y;
#pragma unroll
    for (int i = 0; i < 32; i += 8)
        t[y + i][x] = in[(size_t)(by + y + i) * C + bx + x];
    __syncthreads();
#pragma unroll
    for (int i = 0; i < 32; i += 8) {
        float v = t[x][y + i];
        __nv_bfloat16 h = __float2bfloat16(v);
        size_t o = (size_t)(bx + y + i) * R + by + x;
        oh[o] = h;
        ol[o] = __float2bfloat16(v - __bfloat162float(h));
    }
}
// z-batched 512x512 transpose+split for Wq/Wv/Wo
__global__ void transposeSplit512x3(
    const float* __restrict__ s0, const float* __restrict__ s1,
    const float* __restrict__ s2,
    __nv_bfloat16* __restrict__ h0, __nv_bfloat16* __restrict__ l0,
    __nv_bfloat16* __restrict__ h1, __nv_bfloat16* __restrict__ l1,
    __nv_bfloat16* __restrict__ h2, __nv_bfloat16* __restrict__ l2)
{
    const float* in = blockIdx.z == 0 ? s0 : blockIdx.z == 1 ? s1 : s2;
    __nv_bfloat16* oh = blockIdx.z == 0 ? h0 : blockIdx.z == 1 ? h1 : h2;
    __nv_bfloat16* ol = blockIdx.z == 0 ? l0 : blockIdx.z == 1 ? l1 : l2;
    __shared__ float t[32][33];
    int bx = blockIdx.x * 32, by = blockIdx.y * 32;
    int x = threadIdx.x, y = threadIdx.y;
#pragma unroll
    for (int i = 0; i < 32; i += 8)
        t[y + i][x] = in[(size_t)(by + y + i) * 512 + bx + x];
    __syncthreads();
#pragma unroll
    for (int i = 0; i < 32; i += 8) {
        float v = t[x][y + i];
        __nv_bfloat16 h = __float2bfloat16(v);
        size_t o = (size_t)(bx + y + i) * 512 + by + x;
        oh[o] = h;
        ol[o] = __float2bfloat16(v - __bfloat162float(h));
    }
}
__global__ void transposeK(const float* __restrict__ in, float* __restrict__ out,
                           int R, int C)
{
    __shared__ float t[32][33];
    int bx = blockIdx.x * 32, by = blockIdx.y * 32;
    int x = threadIdx.x, y = threadIdx.y;
#pragma unroll
    for (int i = 0; i < 32; i += 8)
        t[y + i][x] = in[(size_t)(by + y + i) * C + bx + x];
    __syncthreads();
#pragma unroll
    for (int i = 0; i < 32; i += 8)
        out[(size_t)(bx + y + i) * R + by + x] = t[x][y + i];
}
__global__ void splitOnly(const float* __restrict__ in,
                          __nv_bfloat16* __restrict__ oh,
                          __nv_bfloat16* __restrict__ ol, int n4)
{
    int i = blockIdx.x * blockDim.x + threadIdx.x;
    if (i >= n4) return;
    float4 v = ((const float4*)in)[i];
    split_store(v.x, v.y, oh + (size_t)i * 4, ol + (size_t)i * 4);
    split_store(v.z, v.w, oh + (size_t)i * 4 + 2, ol + (size_t)i * 4 + 2);
}

// ---------------- BatchNorm stats: 128 CTAs, fp32 partials ----------------
__global__ void bn_stats_kernel(const __nv_bfloat16* __restrict__ H1h,
                                const __nv_bfloat16* __restrict__ H1l,
                                const float* __restrict__ gamma,
                                const float* __restrict__ beta,
                                float* __restrict__ S, float* __restrict__ T)
{
    __shared__ float ss[16][16], sq[16][16];
    const int col0 = blockIdx.x * 16;
    const int c = threadIdx.x & 15, rg = threadIdx.x >> 4;
    float s = 0.f, q = 0.f;
#pragma unroll 4
    for (int i = 0; i < 128; ++i) {
        size_t idx = (size_t)(rg * 128 + i) * HIDD + col0 + c;
        float v = __bfloat162float(H1h[idx]) + __bfloat162float(H1l[idx]);
        s += v;
        q += v * v;
    }
    ss[rg][c] = s;
    sq[rg][c] = q;
    __syncthreads();
    if (threadIdx.x < 16) {
        float st = 0.f, qt = 0.f;
#pragma unroll
        for (int g = 0; g < 16; ++g) { st += ss[g][threadIdx.x]; qt += sq[g][threadIdx.x]; }
        float mu = st / 2048.f;
        float var = qt / 2048.f - mu * mu;
        float rstd = rsqrtf(var + 1e-5f);
        float sc = gamma[col0 + threadIdx.x] * rstd;
        S[col0 + threadIdx.x] = sc;
        T[col0 + threadIdx.x] = beta[col0 + threadIdx.x] - mu * sc;
    }
}

// ---------------- fold BN into W2 ----------------
__global__ void w2prep(const float* __restrict__ W2T, const float* __restrict__ S,
                       const float* __restrict__ T, const float* __restrict__ b2,
                       __nv_bfloat16* __restrict__ W2h,
                       __nv_bfloat16* __restrict__ W2l,
                       float* __restrict__ bias2)
{
    int n = blockIdx.x * 8 + (threadIdx.x >> 5);
    int lane = threadIdx.x & 31;
    const float* row = W2T + (size_t)n * HIDD;
    float tsum = 0.f;
    for (int k = lane * 4; k < HIDD; k += 128) {
        float4 w = *(const float4*)(row + k);
        float4 s = *(const float4*)(S + k);
        float4 t4 = *(const float4*)(T + k);
        tsum += t4.x * w.x + t4.y * w.y + t4.z * w.z + t4.w * w.w;
        size_t o = (size_t)n * HIDD + k;
        split_store(w.x * s.x, w.y * s.y, W2h + o, W2l + o);
        split_store(w.z * s.z, w.w * s.w, W2h + o + 2, W2l + o + 2);
    }
#pragma unroll
    for (int off = 16; off; off >>= 1)
        tsum += __shfl_xor_sync(0xffffffffu, tsum, off);
    if (lane == 0) bias2[n] = b2[n] + tsum;
}

// ---------------- single-pass flash attention over neighbors ---------------
// One CTA per batch. neighbors read ONCE (vs twice before).
// Tile = 32 rows x 512 d, stride 516 floats (conflict-free), double-buffered
// cp.async. Online softmax per head; accumulator: thread t owns d={2t,2t+1}
// for all 8 heads (16 regs).
#define ATT_TSTR 516
#define ATT_TILEF (32 * ATT_TSTR)          // 16512 floats per buffer
#define ATT_TILE_OFF 6432
#define ATTN_SMEM ((ATT_TILE_OFF + 2 * ATT_TILEF) * 4)   // 157824 B

__global__ __launch_bounds__(256) void attn_kernel(
    const float* __restrict__ nb, const float* __restrict__ r,
    const int* __restrict__ lengths,
    __nv_bfloat16* __restrict__ ch, __nv_bfloat16* __restrict__ cl)
{
    extern __shared__ float sm[];
    float* r_s  = sm;                  // [8][512]
    float* sc   = sm + 4096;           // [32][8] scores -> p
    float* stg  = sm + 4352;           // [8][32][8] cross-warp staging
    float* mh   = sm + 6400;           // [8]
    float* ssum = sm + 6408;           // [8]
    float* alf  = sm + 6416;           // [8]
    float* tile = sm + ATT_TILE_OFF;   // 2 x [32][516]

    const int b = blockIdx.x, tid = threadIdx.x;
    const int wid = tid >> 5, lane = tid & 31;
    const float NEG = -INFINITY;
    const float* nbb = nb + (size_t)b * Nn * Dd;
    const int len = lengths[b];

    {
        const float4* rg = (const float4*)(r + (size_t)b * 4096);
        float4* r4 = (float4*)r_s;
        for (int i = tid; i < 1024; i += 256) r4[i] = rg[i];
    }
    if (tid < 8) { mh[tid] = NEG; ssum[tid] = 0.f; }

    const uint32_t tbase = smem_u32(sm) + ATT_TILE_OFF * 4;
    auto issueTile = [&](int t) {
        uint32_t dst = tbase + (uint32_t)(t & 1) * (ATT_TILEF * 4);
        const float* src = nbb + (size_t)t * 32 * Dd;
#pragma unroll
        for (int i = 0; i < 16; i++) {
            int idx = tid + i * 256;           // 0..4095
            int n = idx >> 7, c = idx & 127;
            cpasync16(dst + (uint32_t)n * (ATT_TSTR * 4) + (uint32_t)c * 16,
                      src + (size_t)n * Dd + c * 4);
        }
        cpcommit();
    };
    issueTile(0);
    issueTile(1);

    float acc[8][2];
#pragma unroll
    for (int h = 0; h < 8; h++) { acc[h][0] = 0.f; acc[h][1] = 0.f; }
    const int d0 = 2 * tid;

    for (int t = 0; t < 4; ++t) {
        if (t < 3) cpwait<1>(); else cpwait<0>();
        __syncthreads();
        const float* tb = tile + (t & 1) * ATT_TILEF;

        // ---- scores: warp = d-part (64 floats), lane = n ----
        {
            float part[8] = {0.f, 0.f, 0.f, 0.f, 0.f, 0.f, 0.f, 0.f};
            const float4* trow = (const float4*)(tb + lane * ATT_TSTR + wid * 64);
            const float4* rb = (const float4*)r_s + wid * 16;
#pragma unroll
            for (int i = 0; i < 16; i++) {
                float4 tv = trow[i];
#pragma unroll
                for (int h = 0; h < 8; h++) {
                    float4 rv = rb[h * 128 + i];
                    part[h] += tv.x * rv.x + tv.y * rv.y + tv.z * rv.z + tv.w * rv.w;
                }
            }
            float* sp = stg + (wid * 32 + lane) * 8;
            *(float4*)sp = make_float4(part[0], part[1], part[2], part[3]);
            *(float4*)(sp + 4) = make_float4(part[4], part[5], part[6], part[7]);
        }
        __syncthreads();
        // ---- reduce across 8 d-parts: thread (n = tid>>3, h = tid&7) ----
        {
            int n = tid >> 3, h = tid & 7;
            float s = 0.f;
#pragma unroll
            for (int dp = 0; dp < 8; dp++) s += stg[dp * 256 + n * 8 + h];
            sc[n * 8 + h] = s;
        }
        __syncthreads();
        // ---- online softmax update: warp = head ----
        {
            int h = wid, n = lane;
            bool valid = (t * 32 + n) < len;
            float v = valid ? sc[n * 8 + h] : NEG;
            float mx = v;
#pragma unroll
            for (int o = 16; o; o >>= 1)
                mx = fmaxf(mx, __shfl_xor_sync(0xffffffffu, mx, o));
            float m_old = mh[h];
            float m_new = fmaxf(m_old, mx);
            float p = valid ? expf(v - m_new) : 0.f;
            float ps = p;
#pragma unroll
            for (int o = 16; o; o >>= 1)
                ps += __shfl_xor_sync(0xffffffffu, ps, o);
            float a = (m_old == NEG) ? 0.f : expf(m_old - m_new);
            if (lane == 0) {
                mh[h] = m_new;
                ssum[h] = ssum[h] * a + ps;
                alf[h] = a;
            }
            sc[n * 8 + h] = p;
        }
        __syncthreads();
        // ---- accumulate: thread owns d pair {2t,2t+1} for all heads ----
        {
#pragma unroll
            for (int h = 0; h < 8; h++) {
                float a = alf[h];
                acc[h][0] *= a;
                acc[h][1] *= a;
            }
#pragma unroll 8
            for (int n = 0; n < 32; ++n) {
                float2 tv = *(const float2*)(tb + n * ATT_TSTR + d0);
                float4 p0 = *(const float4*)(sc + n * 8);
                float4 p1 = *(const float4*)(sc + n * 8 + 4);
                acc[0][0] += p0.x * tv.x; acc[0][1] += p0.x * tv.y;
                acc[1][0] += p0.y * tv.x; acc[1][1] += p0.y * tv.y;
                acc[2][0] += p0.z * tv.x; acc[2][1] += p0.z * tv.y;
                acc[3][0] += p0.w * tv.x; acc[3][1] += p0.w * tv.y;
                acc[4][0] += p1.x * tv.x; acc[4][1] += p1.x * tv.y;
                acc[5][0] += p1.y * tv.x; acc[5][1] += p1.y * tv.y;
                acc[6][0] += p1.z * tv.x; acc[6][1] += p1.z * tv.y;
                acc[7][0] += p1.w * tv.x; acc[7][1] += p1.w * tv.y;
            }
        }
        __syncthreads();
        if (t + 2 < 4) issueTile(t + 2);
    }

    __nv_bfloat16* cbh = ch + (size_t)b * 4096;
    __nv_bfloat16* cbl = cl + (size_t)b * 4096;
#pragma unroll
    for (int h = 0; h < 8; h++) {
        float inv = 1.f / ssum[h];
        split_store(acc[h][0] * inv, acc[h][1] * inv,
                    cbh + h * 512 + d0, cbl + h * 512 + d0);
    }
}

// ---------------- launch ----------------
extern "C" void kernel_launch(void* const* d_in, const int* in_sizes, int n_in,
                              void* d_out, int out_size)
{
    const float* catalog = (const float*)d_in[0];
    const float* neighbors = (const float*)d_in[1];
    const int*   lengths = (const int*)d_in[2];
    const float* W1 = (const float*)d_in[3];
    const float* b1 = (const float*)d_in[4];
    const float* gamma = (const float*)d_in[5];
    const float* beta = (const float*)d_in[6];
    const float* W2 = (const float*)d_in[7];
    const float* b2 = (const float*)d_in[8];
    const float* W3 = (const float*)d_in[9];
    const float* b3 = (const float*)d_in[10];
    const float* Wq = (const float*)d_in[11];
    const float* bq = (const float*)d_in[12];
    const float* Wk = (const float*)d_in[13];
    // d_in[14] = bk: constant per (b,h) across n -> cancels in softmax
    const float* Wv = (const float*)d_in[15];
    const float* bv = (const float*)d_in[16];
    const float* Wo = (const float*)d_in[17];
    const float* bo = (const float*)d_in[18];
    float* out = (float*)d_out;

    __nv_bfloat16 *cath, *catl, *H1h, *H1l, *H2h, *H2l, *embh, *embl;
    __nv_bfloat16 *qh, *ql, *ch, *cl, *ctxh, *ctxl;
    __nv_bfloat16 *W1Th, *W1Tl, *W2h, *W2l, *W3Th, *W3Tl;
    __nv_bfloat16 *WqTh, *WqTl, *Wkh, *Wkl, *WvTh, *WvTl, *WoTh, *WoTl;
    float *r, *W2T, *S, *T, *bias2;
    cudaGetSymbolAddress((void**)&cath, g_cath);
    cudaGetSymbolAddress((void**)&catl, g_catl);
    cudaGetSymbolAddress((void**)&H1h, g_H1h);
    cudaGetSymbolAddress((void**)&H1l, g_H1l);
    cudaGetSymbolAddress((void**)&H2h, g_H2h);
    cudaGetSymbolAddress((void**)&H2l, g_H2l);
    cudaGetSymbolAddress((void**)&embh, g_embh);
    cudaGetSymbolAddress((void**)&embl, g_embl);
    cudaGetSymbolAddress((void**)&qh, g_qh);
    cudaGetSymbolAddress((void**)&ql, g_ql);
    cudaGetSymbolAddress((void**)&ch, g_ch);
    cudaGetSymbolAddress((void**)&cl, g_cl);
    cudaGetSymbolAddress((void**)&ctxh, g_ctxh);
    cudaGetSymbolAddress((void**)&ctxl, g_ctxl);
    cudaGetSymbolAddress((void**)&W1Th, g_W1Th);
    cudaGetSymbolAddress((void**)&W1Tl, g_W1Tl);
    cudaGetSymbolAddress((void**)&W2h, g_W2h);
    cudaGetSymbolAddress((void**)&W2l, g_W2l);
    cudaGetSymbolAddress((void**)&W3Th, g_W3Th);
    cudaGetSymbolAddress((void**)&W3Tl, g_W3Tl);
    cudaGetSymbolAddress((void**)&WqTh, g_WqTh);
    cudaGetSymbolAddress((void**)&WqTl, g_WqTl);
    cudaGetSymbolAddress((void**)&Wkh, g_Wkh);
    cudaGetSymbolAddress((void**)&Wkl, g_Wkl);
    cudaGetSymbolAddress((void**)&WvTh, g_WvTh);
    cudaGetSymbolAddress((void**)&WvTl, g_WvTl);
    cudaGetSymbolAddress((void**)&WoTh, g_WoTh);
    cudaGetSymbolAddress((void**)&WoTl, g_WoTl);
    cudaGetSymbolAddress((void**)&r, g_r);
    cudaGetSymbolAddress((void**)&W2T, g_W2T);
    cudaGetSymbolAddress((void**)&S, g_bnS);
    cudaGetSymbolAddress((void**)&T, g_bnT);
    cudaGetSymbolAddress((void**)&bias2, g_bias2);

    constexpr int SM128 = 3 * (20480 + 2 * 128 * 80);  // 122880
    constexpr int SM64  = 3 * (20480 + 2 * 64 * 80);   // 92160
    cudaFuncSetAttribute(bgemm<128, true, 1>,
                         cudaFuncAttributeMaxDynamicSharedMemorySize, SM128);
    cudaFuncSetAttribute(bgemm<64, false, 1>,
                         cudaFuncAttributeMaxDynamicSharedMemorySize, SM64);
    cudaFuncSetAttribute(bgemm<64, false, 0>,
                         cudaFuncAttributeMaxDynamicSharedMemorySize, SM64);
    cudaFuncSetAttribute(attn_kernel,
                         cudaFuncAttributeMaxDynamicSharedMemorySize, ATTN_SMEM);

    // ---- prep ----
    transposeSplit<<<dim3(HIDD / 32, Dd / 32), dim3(32, 8)>>>(W1, W1Th, W1Tl,
                                                              Dd, HIDD);
    transposeK<<<dim3(HIDD / 32, HIDD / 32), dim3(32, 8)>>>(W2, W2T, HIDD, HIDD);
    transposeSplit<<<dim3(Dd / 32, HIDD / 32), dim3(32, 8)>>>(W3, W3Th, W3Tl,
                                                              HIDD, Dd);
    transposeSplit512x3<<<dim3(16, 16, 3), dim3(32, 8)>>>(
        Wq, Wv, Wo, WqTh, WqTl, WvTh, WvTl, WoTh, WoTl);
    splitOnly<<<(Dd * Dd / 4) / 256, 256>>>(Wk, Wkh, Wkl, Dd * Dd / 4);
    splitOnly<<<(Bb * Dd / 4) / 256, 256>>>(catalog, cath, catl, Bb * Dd / 4);

    // ---- FFN ----
    bgemm<128, true, 1><<<dim3(16, 16, 1), 256, SM128>>>(
        cath, catl, Dd, 0, W1Th, W1Tl, Dd, 0,
        nullptr, H1h, H1l, HIDD, 0, b1, 0, Dd, 1.f);
    bn_stats_kernel<<<HIDD / 16, 256>>>(H1h, H1l, gamma, beta, S, T);
    w2prep<<<HIDD / 8, 256>>>(W2T, S, T, b2, W2h, W2l, bias2);
    bgemm<128, true, 1><<<dim3(16, 16, 1), 256, SM128>>>(
        H1h, H1l, HIDD, 0, W2h, W2l, HIDD, 0,
        nullptr, H2h, H2l, HIDD, 0, bias2, 0, HIDD, 1.f);
    bgemm<64, false, 1><<<dim3(8, 16, 1), 256, SM64>>>(
        H2h, H2l, HIDD, 0, W3Th, W3Tl, HIDD, 0,
        nullptr, embh, embl, Dd, 0, b3, 0, HIDD, 1.f);

    // ---- q = emb @ Wq + bq ----
    bgemm<64, false, 1><<<dim3(8, 16, 1), 256, SM64>>>(
        embh, embl, Dd, 0, WqTh, WqTl, Dd, 0,
        nullptr, qh, ql, Dd, 0, bq, 0, Dd, 1.f);

    // ---- r[b,h,d] = (1/8) * sum_j q[b,h,j] * Wk[d, h*64+j] ----
    bgemm<64, false, 0><<<dim3(8, 16, 8), 256, SM64>>>(
        qh, ql, Dd, DHh, Wkh, Wkl, Dd, DHh,
        r, nullptr, nullptr, Hh * Dd, Dd, nullptr, 0, DHh, 0.125f);

    // ---- single-pass flash attention (writes split c) ----
    attn_kernel<<<Bb, 256, ATTN_SMEM>>>(neighbors, r, lengths, ch, cl);

    // ---- ctx = c @ Wv + bv (per head) ----
    bgemm<64, false, 1><<<dim3(1, 16, 8), 256, SM64>>>(
        ch, cl, Hh * Dd, Dd, WvTh, WvTl, Dd, (long)DHh * Dd,
        nullptr, ctxh, ctxl, Dd, DHh, bv, DHh, Dd, 1.f);

    // ---- out = ctx @ Wo + bo ----
    bgemm<64, false, 0><<<dim3(8, 16, 1), 256, SM64>>>(
        ctxh, ctxl, Dd, 0, WoTh, WoTl, Dd, 0,
        out, nullptr, nullptr, Dd, 0, bo, 0, Dd, 1.f);
}

// round 8
// speedup vs baseline: 5.4135x; 1.1686x over previous
#include <cuda_runtime.h>
#include <cuda_bf16.h>
#include <math.h>
#include <stdint.h>

// Problem dims (fixed)
#define Bb   2048
#define Nn   128
#define Dd   512
#define HIDD 2048
#define Hh   8
#define DHh  64

// ---------------- scratch (device globals; no allocations) ----------------
__device__ __nv_bfloat16 g_cath[Bb * Dd],  g_catl[Bb * Dd];
__device__ __nv_bfloat16 g_H1h[Bb * HIDD], g_H1l[Bb * HIDD];
__device__ __nv_bfloat16 g_H2h[Bb * HIDD], g_H2l[Bb * HIDD];
__device__ __nv_bfloat16 g_embh[Bb * Dd],  g_embl[Bb * Dd];
__device__ __nv_bfloat16 g_qh[Bb * Dd],    g_ql[Bb * Dd];
__device__ __nv_bfloat16 g_ch[Bb * Hh * Dd], g_cl[Bb * Hh * Dd];
__device__ __nv_bfloat16 g_ctxh[Bb * Dd],  g_ctxl[Bb * Dd];
__device__ __nv_bfloat16 g_W1Th[HIDD * Dd], g_W1Tl[HIDD * Dd];
__device__ __nv_bfloat16 g_W2h[HIDD * HIDD], g_W2l[HIDD * HIDD];
__device__ __nv_bfloat16 g_W3Th[Dd * HIDD], g_W3Tl[Dd * HIDD];
__device__ __nv_bfloat16 g_WqTh[Dd * Dd],  g_WqTl[Dd * Dd];
__device__ __nv_bfloat16 g_Wkh[Dd * Dd],   g_Wkl[Dd * Dd];
__device__ __nv_bfloat16 g_WvTh[Dd * Dd],  g_WvTl[Dd * Dd];
__device__ __nv_bfloat16 g_WoTh[Dd * Dd],  g_WoTl[Dd * Dd];
__device__ float g_r[Bb * Hh * Dd];
__device__ float g_W2T[HIDD * HIDD];
__device__ float g_bnS[HIDD];
__device__ float g_bnT[HIDD];
__device__ float g_bias2[HIDD];

// ================= helpers =================
__device__ __forceinline__ uint32_t smem_u32(const void* p) {
    uint32_t a;
    asm("{ .reg .u64 t; cvta.to.shared.u64 t, %1; cvt.u32.u64 %0, t; }"
        : "=r"(a) : "l"(p));
    return a;
}
__device__ __forceinline__ void cpasync16(uint32_t dst, const void* src) {
    asm volatile("cp.async.cg.shared.global [%0], [%1], 16;"
                 :: "r"(dst), "l"(src) : "memory");
}
__device__ __forceinline__ void cpcommit() {
    asm volatile("cp.async.commit_group;" ::: "memory");
}
template <int N>
__device__ __forceinline__ void cpwait() {
    asm volatile("cp.async.wait_group %0;" :: "n"(N) : "memory");
}
__device__ __forceinline__ void ldm4(uint32_t* r, uint32_t addr) {
    asm volatile("ldmatrix.sync.aligned.m8n8.x4.shared.b16 {%0,%1,%2,%3}, [%4];"
                 : "=r"(r[0]), "=r"(r[1]), "=r"(r[2]), "=r"(r[3]) : "r"(addr));
}
__device__ __forceinline__ void mma16816(float* c, const uint32_t* a,
                                         const uint32_t* b) {
    asm volatile(
        "mma.sync.aligned.m16n8k16.row.col.f32.bf16.bf16.f32 "
        "{%0,%1,%2,%3}, {%4,%5,%6,%7}, {%8,%9}, {%0,%1,%2,%3};"
        : "+f"(c[0]), "+f"(c[1]), "+f"(c[2]), "+f"(c[3])
        : "r"(a[0]), "r"(a[1]), "r"(a[2]), "r"(a[3]), "r"(b[0]), "r"(b[1]));
}
__device__ __forceinline__ void split_store(float x, float y,
                                            __nv_bfloat16* ph,
                                            __nv_bfloat16* pl) {
    __nv_bfloat162 h = __floats2bfloat162_rn(x, y);
    float rx = x - __bfloat162float(h.x);
    float ry = y - __bfloat162float(h.y);
    __nv_bfloat162 l = __floats2bfloat162_rn(rx, ry);
    *reinterpret_cast<uint32_t*>(ph) = *reinterpret_cast<uint32_t*>(&h);
    *reinterpret_cast<uint32_t*>(pl) = *reinterpret_cast<uint32_t*>(&l);
}

// ================= bf16x3 GEMM, TBK=64, 3-stage cp.async, 1 sync/iter ======
// C[z] = scale * A[z] @ B[z]^T + bias[z]; operands pre-split bf16 hi/lo.
// D = Ah*Bh + Ah*Bl + Al*Bh, fp32 accum. CTA tile 128 x TBN, K-tile 64.
template <int TBN, bool DOTANH, int OUTMODE>
__global__ void __launch_bounds__(256)
bgemm(const __nv_bfloat16* __restrict__ Ah, const __nv_bfloat16* __restrict__ Al,
      int lda, long sAz,
      const __nv_bfloat16* __restrict__ Bh, const __nv_bfloat16* __restrict__ Bl,
      int ldb, long sBz,
      float* __restrict__ C, __nv_bfloat16* __restrict__ Ch,
      __nv_bfloat16* __restrict__ Cl, int ldc, long sCz,
      const float* __restrict__ bias, long sBiasz, int K, float scale)
{
    constexpr int TBM = 128, TBK = 64;
    constexpr int WN = TBN / 4;
    constexpr int NF = WN / 8;
    constexpr int STRIDE = 144;                // 64 bf16 (128B) + 16B pad
    constexpr int OA_L = TBM * STRIDE;         // 18432
    constexpr int OB_H = 2 * TBM * STRIDE;     // 36864
    constexpr int OB_L = OB_H + TBN * STRIDE;
    constexpr int STAGE = OB_H + 2 * TBN * STRIDE;

    extern __shared__ __align__(16) char dynsm[];
    const uint32_t sb0 = smem_u32(dynsm);

    const int tid = threadIdx.x, wid = tid >> 5, lane = tid & 31;
    const int wm = wid >> 2, wn = wid & 3;

    Ah += (size_t)blockIdx.z * sAz + (size_t)blockIdx.y * TBM * lda;
    Al += (size_t)blockIdx.z * sAz + (size_t)blockIdx.y * TBM * lda;
    Bh += (size_t)blockIdx.z * sBz + (size_t)blockIdx.x * TBN * ldb;
    Bl += (size_t)blockIdx.z * sBz + (size_t)blockIdx.x * TBN * ldb;

    const uint32_t aoff = (uint32_t)(wm * 64 + (lane & 15)) * STRIDE
                        + (uint32_t)((lane >> 4) * 8) * 2;
    const uint32_t boff = (uint32_t)(wn * WN + ((lane >> 4) & 1) * 8 + (lane & 7))
                          * STRIDE
                        + (uint32_t)(((lane >> 3) & 1) * 8) * 2;

    float acc[4][NF][4];
#pragma unroll
    for (int i = 0; i < 4; i++)
#pragma unroll
        for (int j = 0; j < NF; j++)
#pragma unroll
            for (int e = 0; e < 4; e++) acc[i][j][e] = 0.f;

    auto issueStage = [&](int kt, int buf) {
        const uint32_t sb = sb0 + buf * STAGE;
        const int k0 = kt * TBK;
#pragma unroll
        for (int i = 0; i < 4; i++) {            // A: 128 rows x 8 chunks
            int idx = tid + i * 256;
            int r = idx >> 3, cc = idx & 7;
            const size_t go = (size_t)r * lda + k0 + cc * 8;
            const uint32_t so = (uint32_t)r * STRIDE + cc * 16;
            cpasync16(sb + so, Ah + go);
            cpasync16(sb + OA_L + so, Al + go);
        }
#pragma unroll
        for (int i = 0; i < TBN / 32; i++) {     // B: TBN rows x 8 chunks
            int idx = tid + i * 256;
            int r = idx >> 3, cc = idx & 7;
            const size_t go = (size_t)r * ldb + k0 + cc * 8;
            const uint32_t so = (uint32_t)r * STRIDE + cc * 16;
            cpasync16(sb + OB_H + so, Bh + go);
            cpasync16(sb + OB_L + so, Bl + go);
        }
        cpcommit();
    };

    auto compute = [&](int buf) {
        const uint32_t sb = sb0 + buf * STAGE;
#pragma unroll
        for (int kh = 0; kh < 4; ++kh) {
            const uint32_t kb = (uint32_t)kh * 32;
            uint32_t bh[NF][2], bl[NF][2];
#pragma unroll
            for (int p = 0; p < NF / 2; ++p) {
                uint32_t r4[4];
                ldm4(r4, sb + OB_H + boff + p * 16u * STRIDE + kb);
                bh[2 * p][0] = r4[0]; bh[2 * p][1] = r4[1];
                bh[2 * p + 1][0] = r4[2]; bh[2 * p + 1][1] = r4[3];
                ldm4(r4, sb + OB_L + boff + p * 16u * STRIDE + kb);
                bl[2 * p][0] = r4[0]; bl[2 * p][1] = r4[1];
                bl[2 * p + 1][0] = r4[2]; bl[2 * p + 1][1] = r4[3];
            }
#pragma unroll
            for (int mf = 0; mf < 4; ++mf) {
                uint32_t ah[4], al[4];
                ldm4(ah, sb + aoff + (uint32_t)mf * 16u * STRIDE + kb);
                ldm4(al, sb + OA_L + aoff + (uint32_t)mf * 16u * STRIDE + kb);
#pragma unroll
                for (int nf = 0; nf < NF; ++nf) {
                    mma16816(acc[mf][nf], ah, bh[nf]);
                    mma16816(acc[mf][nf], ah, bl[nf]);
                    mma16816(acc[mf][nf], al, bh[nf]);
                }
            }
        }
    };

    const int KT = K / TBK;
    issueStage(0, 0);
    if (KT > 1) issueStage(1, 1);
    for (int kt = 0; kt < KT; ++kt) {
        if (kt + 1 < KT) cpwait<1>(); else cpwait<0>();
        __syncthreads();
        if (kt + 2 < KT) issueStage(kt + 2, (kt + 2) % 3);
        compute(kt % 3);
    }

    const float* bp = bias ? bias + (size_t)blockIdx.z * sBiasz
                           + (size_t)blockIdx.x * TBN
                         : nullptr;
    const size_t cbase = (size_t)blockIdx.z * sCz
                       + (size_t)blockIdx.y * TBM * ldc
                       + (size_t)blockIdx.x * TBN;
    const int r1 = lane >> 2, c1 = (lane & 3) * 2;
#pragma unroll
    for (int mf = 0; mf < 4; ++mf) {
#pragma unroll
        for (int nf = 0; nf < NF; ++nf) {
            int col = wn * WN + nf * 8 + c1;
            float bx = bp ? bp[col] : 0.f, by = bp ? bp[col + 1] : 0.f;
            int row0 = wm * 64 + mf * 16 + r1;
            float2 v0, v1;
            v0.x = acc[mf][nf][0] * scale + bx;
            v0.y = acc[mf][nf][1] * scale + by;
            v1.x = acc[mf][nf][2] * scale + bx;
            v1.y = acc[mf][nf][3] * scale + by;
            if (DOTANH) {
                v0.x = tanhf(v0.x); v0.y = tanhf(v0.y);
                v1.x = tanhf(v1.x); v1.y = tanhf(v1.y);
            }
            size_t o0 = cbase + (size_t)row0 * ldc + col;
            size_t o1 = cbase + (size_t)(row0 + 8) * ldc + col;
            if (OUTMODE == 0) {
                *(float2*)(C + o0) = v0;
                *(float2*)(C + o1) = v1;
            } else {
                split_store(v0.x, v0.y, Ch + o0, Cl + o0);
                split_store(v1.x, v1.y, Ch + o1, Cl + o1);
            }
        }
    }
}

// ---------------- weight prep kernels ----------------
__global__ void transposeSplit(const float* __restrict__ in,
                               __nv_bfloat16* __restrict__ oh,
                               __nv_bfloat16* __restrict__ ol, int R, int C)
{
    __shared__ float t[32][33];
    int bx = blockIdx.x * 32, by = blockIdx.y * 32;
    int x = threadIdx.x, y = threadIdx.y;
#pragma unroll
    for (int i = 0; i < 32; i += 8)
        t[y + i][x] = in[(size_t)(by + y + i) * C + bx + x];
    __syncthreads();
#pragma unroll
    for (int i = 0; i < 32; i += 8) {
        float v = t[x][y + i];
        __nv_bfloat16 h = __float2bfloat16(v);
        size_t o = (size_t)(bx + y + i) * R + by + x;
        oh[o] = h;
        ol[o] = __float2bfloat16(v - __bfloat162float(h));
    }
}
__global__ void transposeSplit512x3(
    const float* __restrict__ s0, const float* __restrict__ s1,
    const float* __restrict__ s2,
    __nv_bfloat16* __restrict__ h0, __nv_bfloat16* __restrict__ l0,
    __nv_bfloat16* __restrict__ h1, __nv_bfloat16* __restrict__ l1,
    __nv_bfloat16* __restrict__ h2, __nv_bfloat16* __restrict__ l2)
{
    const float* in = blockIdx.z == 0 ? s0 : blockIdx.z == 1 ? s1 : s2;
    __nv_bfloat16* oh = blockIdx.z == 0 ? h0 : blockIdx.z == 1 ? h1 : h2;
    __nv_bfloat16* ol = blockIdx.z == 0 ? l0 : blockIdx.z == 1 ? l1 : l2;
    __shared__ float t[32][33];
    int bx = blockIdx.x * 32, by = blockIdx.y * 32;
    int x = threadIdx.x, y = threadIdx.y;
#pragma unroll
    for (int i = 0; i < 32; i += 8)
        t[y + i][x] = in[(size_t)(by + y + i) * 512 + bx + x];
    __syncthreads();
#pragma unroll
    for (int i = 0; i < 32; i += 8) {
        float v = t[x][y + i];
        __nv_bfloat16 h = __float2bfloat16(v);
        size_t o = (size_t)(bx + y + i) * 512 + by + x;
        oh[o] = h;
        ol[o] = __float2bfloat16(v - __bfloat162float(h));
    }
}
__global__ void transposeK(const float* __restrict__ in, float* __restrict__ out,
                           int R, int C)
{
    __shared__ float t[32][33];
    int bx = blockIdx.x * 32, by = blockIdx.y * 32;
    int x = threadIdx.x, y = threadIdx.y;
#pragma unroll
    for (int i = 0; i < 32; i += 8)
        t[y + i][x] = in[(size_t)(by + y + i) * C + bx + x];
    __syncthreads();
#pragma unroll
    for (int i = 0; i < 32; i += 8)
        out[(size_t)(bx + y + i) * R + by + x] = t[x][y + i];
}
__global__ void splitOnly(const float* __restrict__ in,
                          __nv_bfloat16* __restrict__ oh,
                          __nv_bfloat16* __restrict__ ol, int n4)
{
    int i = blockIdx.x * blockDim.x + threadIdx.x;
    if (i >= n4) return;
    float4 v = ((const float4*)in)[i];
    split_store(v.x, v.y, oh + (size_t)i * 4, ol + (size_t)i * 4);
    split_store(v.z, v.w, oh + (size_t)i * 4 + 2, ol + (size_t)i * 4 + 2);
}

// ---------------- BatchNorm stats: 128 CTAs, fp32 partials ----------------
__global__ void bn_stats_kernel(const __nv_bfloat16* __restrict__ H1h,
                                const __nv_bfloat16* __restrict__ H1l,
                                const float* __restrict__ gamma,
                                const float* __restrict__ beta,
                                float* __restrict__ S, float* __restrict__ T)
{
    __shared__ float ss[16][16], sq[16][16];
    const int col0 = blockIdx.x * 16;
    const int c = threadIdx.x & 15, rg = threadIdx.x >> 4;
    float s = 0.f, q = 0.f;
#pragma unroll 4
    for (int i = 0; i < 128; ++i) {
        size_t idx = (size_t)(rg * 128 + i) * HIDD + col0 + c;
        float v = __bfloat162float(H1h[idx]) + __bfloat162float(H1l[idx]);
        s += v;
        q += v * v;
    }
    ss[rg][c] = s;
    sq[rg][c] = q;
    __syncthreads();
    if (threadIdx.x < 16) {
        float st = 0.f, qt = 0.f;
#pragma unroll
        for (int g = 0; g < 16; ++g) { st += ss[g][threadIdx.x]; qt += sq[g][threadIdx.x]; }
        float mu = st / 2048.f;
        float var = qt / 2048.f - mu * mu;
        float rstd = rsqrtf(var + 1e-5f);
        float sc = gamma[col0 + threadIdx.x] * rstd;
        S[col0 + threadIdx.x] = sc;
        T[col0 + threadIdx.x] = beta[col0 + threadIdx.x] - mu * sc;
    }
}

// ---------------- fold BN into W2 ----------------
__global__ void w2prep(const float* __restrict__ W2T, const float* __restrict__ S,
                       const float* __restrict__ T, const float* __restrict__ b2,
                       __nv_bfloat16* __restrict__ W2h,
                       __nv_bfloat16* __restrict__ W2l,
                       float* __restrict__ bias2)
{
    int n = blockIdx.x * 8 + (threadIdx.x >> 5);
    int lane = threadIdx.x & 31;
    const float* row = W2T + (size_t)n * HIDD;
    float tsum = 0.f;
    for (int k = lane * 4; k < HIDD; k += 128) {
        float4 w = *(const float4*)(row + k);
        float4 s = *(const float4*)(S + k);
        float4 t4 = *(const float4*)(T + k);
        tsum += t4.x * w.x + t4.y * w.y + t4.z * w.z + t4.w * w.w;
        size_t o = (size_t)n * HIDD + k;
        split_store(w.x * s.x, w.y * s.y, W2h + o, W2l + o);
        split_store(w.z * s.z, w.w * s.w, W2h + o + 2, W2l + o + 2);
    }
#pragma unroll
    for (int off = 16; off; off >>= 1)
        tsum += __shfl_xor_sync(0xffffffffu, tsum, off);
    if (lane == 0) bias2[n] = b2[n] + tsum;
}

// ---------------- single-pass flash attention, length-pruned ---------------
#define ATT_TSTR 516
#define ATT_TILEF (32 * ATT_TSTR)
#define ATT_TILE_OFF 6432
#define ATTN_SMEM ((ATT_TILE_OFF + 2 * ATT_TILEF) * 4)   // 157824 B

__global__ __launch_bounds__(256) void attn_kernel(
    const float* __restrict__ nb, const float* __restrict__ r,
    const int* __restrict__ lengths,
    __nv_bfloat16* __restrict__ ch, __nv_bfloat16* __restrict__ cl)
{
    extern __shared__ float sm[];
    float* r_s  = sm;                  // [8][512]
    float* sc   = sm + 4096;           // [32][8]
    float* stg  = sm + 4352;           // [8][32][8]
    float* mh   = sm + 6400;           // [8]
    float* ssum = sm + 6408;           // [8]
    float* alf  = sm + 6416;           // [8]
    float* tile = sm + ATT_TILE_OFF;   // 2 x [32][516]

    const int b = blockIdx.x, tid = threadIdx.x;
    const int wid = tid >> 5, lane = tid & 31;
    const float NEG = -INFINITY;
    const float* nbb = nb + (size_t)b * Nn * Dd;
    const int len = lengths[b];
    const int nT = (len + 31) >> 5;    // tiles actually needed (1..4)

    {
        const float4* rg = (const float4*)(r + (size_t)b * 4096);
        float4* r4 = (float4*)r_s;
        for (int i = tid; i < 1024; i += 256) r4[i] = rg[i];
    }
    if (tid < 8) { mh[tid] = NEG; ssum[tid] = 0.f; }

    const uint32_t tbase = smem_u32(sm) + ATT_TILE_OFF * 4;
    auto issueTile = [&](int t) {
        uint32_t dst = tbase + (uint32_t)(t & 1) * (ATT_TILEF * 4);
        const float* src = nbb + (size_t)t * 32 * Dd;
#pragma unroll
        for (int i = 0; i < 16; i++) {
            int idx = tid + i * 256;
            int n = idx >> 7, c = idx & 127;
            cpasync16(dst + (uint32_t)n * (ATT_TSTR * 4) + (uint32_t)c * 16,
                      src + (size_t)n * Dd + c * 4);
        }
        cpcommit();
    };
    issueTile(0);
    if (nT > 1) issueTile(1);

    float acc[8][2];
#pragma unroll
    for (int h = 0; h < 8; h++) { acc[h][0] = 0.f; acc[h][1] = 0.f; }
    const int d0 = 2 * tid;

    for (int t = 0; t < nT; ++t) {
        if (t + 1 < nT) cpwait<1>(); else cpwait<0>();
        __syncthreads();
        const float* tb = tile + (t & 1) * ATT_TILEF;

        // ---- scores: warp = d-part (64 floats), lane = n ----
        {
            float part[8] = {0.f, 0.f, 0.f, 0.f, 0.f, 0.f, 0.f, 0.f};
            const float4* trow = (const float4*)(tb + lane * ATT_TSTR + wid * 64);
            const float4* rb = (const float4*)r_s + wid * 16;
#pragma unroll
            for (int i = 0; i < 16; i++) {
                float4 tv = trow[i];
#pragma unroll
                for (int h = 0; h < 8; h++) {
                    float4 rv = rb[h * 128 + i];
                    part[h] += tv.x * rv.x + tv.y * rv.y + tv.z * rv.z + tv.w * rv.w;
                }
            }
            float* sp = stg + (wid * 32 + lane) * 8;
            *(float4*)sp = make_float4(part[0], part[1], part[2], part[3]);
            *(float4*)(sp + 4) = make_float4(part[4], part[5], part[6], part[7]);
        }
        __syncthreads();
        // ---- reduce across 8 d-parts ----
        {
            int n = tid >> 3, h = tid & 7;
            float s = 0.f;
#pragma unroll
            for (int dp = 0; dp < 8; dp++) s += stg[dp * 256 + n * 8 + h];
            sc[n * 8 + h] = s;
        }
        __syncthreads();
        // ---- online softmax update: warp = head ----
        {
            int h = wid, n = lane;
            bool valid = (t * 32 + n) < len;
            float v = valid ? sc[n * 8 + h] : NEG;
            float mx = v;
#pragma unroll
            for (int o = 16; o; o >>= 1)
                mx = fmaxf(mx, __shfl_xor_sync(0xffffffffu, mx, o));
            float m_old = mh[h];
            float m_new = fmaxf(m_old, mx);
            float p = valid ? expf(v - m_new) : 0.f;
            float ps = p;
#pragma unroll
            for (int o = 16; o; o >>= 1)
                ps += __shfl_xor_sync(0xffffffffu, ps, o);
            float a = (m_old == NEG) ? 0.f : expf(m_old - m_new);
            if (lane == 0) {
                mh[h] = m_new;
                ssum[h] = ssum[h] * a + ps;
                alf[h] = a;
            }
            sc[n * 8 + h] = p;
        }
        __syncthreads();
        // ---- accumulate ----
        {
#pragma unroll
            for (int h = 0; h < 8; h++) {
                float a = alf[h];
                acc[h][0] *= a;
                acc[h][1] *= a;
            }
#pragma unroll 8
            for (int n = 0; n < 32; ++n) {
                float2 tv = *(const float2*)(tb + n * ATT_TSTR + d0);
                float4 p0 = *(const float4*)(sc + n * 8);
                float4 p1 = *(const float4*)(sc + n * 8 + 4);
                acc[0][0] += p0.x * tv.x; acc[0][1] += p0.x * tv.y;
                acc[1][0] += p0.y * tv.x; acc[1][1] += p0.y * tv.y;
                acc[2][0] += p0.z * tv.x; acc[2][1] += p0.z * tv.y;
                acc[3][0] += p0.w * tv.x; acc[3][1] += p0.w * tv.y;
                acc[4][0] += p1.x * tv.x; acc[4][1] += p1.x * tv.y;
                acc[5][0] += p1.y * tv.x; acc[5][1] += p1.y * tv.y;
                acc[6][0] += p1.z * tv.x; acc[6][1] += p1.z * tv.y;
                acc[7][0] += p1.w * tv.x; acc[7][1] += p1.w * tv.y;
            }
        }
        __syncthreads();
        if (t + 2 < nT) issueTile(t + 2);
    }

    __nv_bfloat16* cbh = ch + (size_t)b * 4096;
    __nv_bfloat16* cbl = cl + (size_t)b * 4096;
#pragma unroll
    for (int h = 0; h < 8; h++) {
        float inv = 1.f / ssum[h];
        split_store(acc[h][0] * inv, acc[h][1] * inv,
                    cbh + h * 512 + d0, cbl + h * 512 + d0);
    }
}

// ---------------- launch ----------------
extern "C" void kernel_launch(void* const* d_in, const int* in_sizes, int n_in,
                              void* d_out, int out_size)
{
    const float* catalog = (const float*)d_in[0];
    const float* neighbors = (const float*)d_in[1];
    const int*   lengths = (const int*)d_in[2];
    const float* W1 = (const float*)d_in[3];
    const float* b1 = (const float*)d_in[4];
    const float* gamma = (const float*)d_in[5];
    const float* beta = (const float*)d_in[6];
    const float* W2 = (const float*)d_in[7];
    const float* b2 = (const float*)d_in[8];
    const float* W3 = (const float*)d_in[9];
    const float* b3 = (const float*)d_in[10];
    const float* Wq = (const float*)d_in[11];
    const float* bq = (const float*)d_in[12];
    const float* Wk = (const float*)d_in[13];
    // d_in[14] = bk: constant per (b,h) across n -> cancels in softmax
    const float* Wv = (const float*)d_in[15];
    const float* bv = (const float*)d_in[16];
    const float* Wo = (const float*)d_in[17];
    const float* bo = (const float*)d_in[18];
    float* out = (float*)d_out;

    __nv_bfloat16 *cath, *catl, *H1h, *H1l, *H2h, *H2l, *embh, *embl;
    __nv_bfloat16 *qh, *ql, *ch, *cl, *ctxh, *ctxl;
    __nv_bfloat16 *W1Th, *W1Tl, *W2h, *W2l, *W3Th, *W3Tl;
    __nv_bfloat16 *WqTh, *WqTl, *Wkh, *Wkl, *WvTh, *WvTl, *WoTh, *WoTl;
    float *r, *W2T, *S, *T, *bias2;
    cudaGetSymbolAddress((void**)&cath, g_cath);
    cudaGetSymbolAddress((void**)&catl, g_catl);
    cudaGetSymbolAddress((void**)&H1h, g_H1h);
    cudaGetSymbolAddress((void**)&H1l, g_H1l);
    cudaGetSymbolAddress((void**)&H2h, g_H2h);
    cudaGetSymbolAddress((void**)&H2l, g_H2l);
    cudaGetSymbolAddress((void**)&embh, g_embh);
    cudaGetSymbolAddress((void**)&embl, g_embl);
    cudaGetSymbolAddress((void**)&qh, g_qh);
    cudaGetSymbolAddress((void**)&ql, g_ql);
    cudaGetSymbolAddress((void**)&ch, g_ch);
    cudaGetSymbolAddress((void**)&cl, g_cl);
    cudaGetSymbolAddress((void**)&ctxh, g_ctxh);
    cudaGetSymbolAddress((void**)&ctxl, g_ctxl);
    cudaGetSymbolAddress((void**)&W1Th, g_W1Th);
    cudaGetSymbolAddress((void**)&W1Tl, g_W1Tl);
    cudaGetSymbolAddress((void**)&W2h, g_W2h);
    cudaGetSymbolAddress((void**)&W2l, g_W2l);
    cudaGetSymbolAddress((void**)&W3Th, g_W3Th);
    cudaGetSymbolAddress((void**)&W3Tl, g_W3Tl);
    cudaGetSymbolAddress((void**)&WqTh, g_WqTh);
    cudaGetSymbolAddress((void**)&WqTl, g_WqTl);
    cudaGetSymbolAddress((void**)&Wkh, g_Wkh);
    cudaGetSymbolAddress((void**)&Wkl, g_Wkl);
    cudaGetSymbolAddress((void**)&WvTh, g_WvTh);
    cudaGetSymbolAddress((void**)&WvTl, g_WvTl);
    cudaGetSymbolAddress((void**)&WoTh, g_WoTh);
    cudaGetSymbolAddress((void**)&WoTl, g_WoTl);
    cudaGetSymbolAddress((void**)&r, g_r);
    cudaGetSymbolAddress((void**)&W2T, g_W2T);
    cudaGetSymbolAddress((void**)&S, g_bnS);
    cudaGetSymbolAddress((void**)&T, g_bnT);
    cudaGetSymbolAddress((void**)&bias2, g_bias2);

    constexpr int STAGE128 = 36864 + 2 * 128 * 144;  // 73728
    constexpr int STAGE64  = 36864 + 2 * 64 * 144;   // 55296
    constexpr int SM128 = 3 * STAGE128;              // 221184
    constexpr int SM64  = 3 * STAGE64;               // 165888
    cudaFuncSetAttribute(bgemm<128, true, 1>,
                         cudaFuncAttributeMaxDynamicSharedMemorySize, SM128);
    cudaFuncSetAttribute(bgemm<64, false, 1>,
                         cudaFuncAttributeMaxDynamicSharedMemorySize, SM64);
    cudaFuncSetAttribute(bgemm<64, false, 0>,
                         cudaFuncAttributeMaxDynamicSharedMemorySize, SM64);
    cudaFuncSetAttribute(attn_kernel,
                         cudaFuncAttributeMaxDynamicSharedMemorySize, ATTN_SMEM);

    // ---- prep (ordered so launch index 5 = the W1 GEMM for ncu) ----
    transposeK<<<dim3(HIDD / 32, HIDD / 32), dim3(32, 8)>>>(W2, W2T, HIDD, HIDD);
    transposeSplit<<<dim3(HIDD / 32, Dd / 32), dim3(32, 8)>>>(W1, W1Th, W1Tl,
                                                              Dd, HIDD);
    splitOnly<<<(Bb * Dd / 4) / 256, 256>>>(catalog, cath, catl, Bb * Dd / 4);
    transposeSplit<<<dim3(Dd / 32, HIDD / 32), dim3(32, 8)>>>(W3, W3Th, W3Tl,
                                                              HIDD, Dd);
    transposeSplit512x3<<<dim3(16, 16, 3), dim3(32, 8)>>>(
        Wq, Wv, Wo, WqTh, WqTl, WvTh, WvTl, WoTh, WoTl);

    // ---- FFN ----  (launch index 5: the profiled one)
    bgemm<128, true, 1><<<dim3(16, 16, 1), 256, SM128>>>(
        cath, catl, Dd, 0, W1Th, W1Tl, Dd, 0,
        nullptr, H1h, H1l, HIDD, 0, b1, 0, Dd, 1.f);
    splitOnly<<<(Dd * Dd / 4) / 256, 256>>>(Wk, Wkh, Wkl, Dd * Dd / 4);
    bn_stats_kernel<<<HIDD / 16, 256>>>(H1h, H1l, gamma, beta, S, T);
    w2prep<<<HIDD / 8, 256>>>(W2T, S, T, b2, W2h, W2l, bias2);
    bgemm<128, true, 1><<<dim3(16, 16, 1), 256, SM128>>>(
        H1h, H1l, HIDD, 0, W2h, W2l, HIDD, 0,
        nullptr, H2h, H2l, HIDD, 0, bias2, 0, HIDD, 1.f);
    bgemm<64, false, 1><<<dim3(8, 16, 1), 256, SM64>>>(
        H2h, H2l, HIDD, 0, W3Th, W3Tl, HIDD, 0,
        nullptr, embh, embl, Dd, 0, b3, 0, HIDD, 1.f);

    // ---- q = emb @ Wq + bq ----
    bgemm<64, false, 1><<<dim3(8, 16, 1), 256, SM64>>>(
        embh, embl, Dd, 0, WqTh, WqTl, Dd, 0,
        nullptr, qh, ql, Dd, 0, bq, 0, Dd, 1.f);

    // ---- r[b,h,d] = (1/8) * sum_j q[b,h,j] * Wk[d, h*64+j] ----
    bgemm<64, false, 0><<<dim3(8, 16, 8), 256, SM64>>>(
        qh, ql, Dd, DHh, Wkh, Wkl, Dd, DHh,
        r, nullptr, nullptr, Hh * Dd, Dd, nullptr, 0, DHh, 0.125f);

    // ---- single-pass flash attention (length-pruned) ----
    attn_kernel<<<Bb, 256, ATTN_SMEM>>>(neighbors, r, lengths, ch, cl);

    // ---- ctx = c @ Wv + bv (per head) ----
    bgemm<64, false, 1><<<dim3(1, 16, 8), 256, SM64>>>(
        ch, cl, Hh * Dd, Dd, WvTh, WvTl, Dd, (long)DHh * Dd,
        nullptr, ctxh, ctxl, Dd, DHh, bv, DHh, Dd, 1.f);

    // ---- out = ctx @ Wo + bo ----
    bgemm<64, false, 0><<<dim3(8, 16, 1), 256, SM64>>>(
        ctxh, ctxl, Dd, 0, WoTh, WoTl, Dd, 0,
        out, nullptr, nullptr, Dd, 0, bo, 0, Dd, 1.f);
}